// round 14
// baseline (speedup 1.0000x reference)
#include <cuda_runtime.h>
#include <cuda_bf16.h>
#include <cuda_fp16.h>
#include <cstdint>

static constexpr int NB = 4, NT = 1568, NC = 512, NH = 8, DH = 64;
static constexpr int NM = NB * NT;   // 6272
static constexpr int N2 = NC * NC;   // 262144
static constexpr float LOG2E = 1.4426950408889634f;

// ---------------- scratch ---------------------------------------------------
__device__ float g_t1 [NB*NT*NC];
__device__ float g_t2 [NB*NT*NC];
__device__ float g_t1f[NB*NT*NC];
__device__ float g_t2f[NB*NT*NC];
__device__ float g_th1[NB*NT*NC/2];
__device__ float g_th2[NB*NT*NC/2];
__device__ float g_ln1h[NB*NT*NC/2];
__device__ float g_ln2h[NB*NT*NC/2];
__device__ float g_q1h[NB*NT*NC/2];   // e4m3 (oversized, fine)
__device__ float g_k1h[NB*NT*NC/2];
__device__ float g_v1h[NB*NT*NC/2];   // V^T f16: [b][c][tok]
__device__ float g_q2h[NB*NT*NC/2];
__device__ float g_k2h[NB*NT*NC/2];
__device__ float g_v2h[NB*NT*NC/2];
__device__ float g_wh [18*N2/2];
__device__ float g_wf [2*N2];

// ---------------- helpers ---------------------------------------------------
__device__ __forceinline__ uint32_t f2tf(float f) {
    uint32_t u;
    asm("cvt.rna.tf32.f32 %0, %1;\n" : "=r"(u) : "f"(f));
    return u;
}
__device__ __forceinline__ float f2tff(float f) { return __uint_as_float(f2tf(f)); }

__device__ __forceinline__ void mma_bf16(float* c, const uint32_t* a, const uint32_t* b) {
    asm volatile(
        "mma.sync.aligned.m16n8k16.row.col.f32.bf16.bf16.f32 "
        "{%0,%1,%2,%3}, {%4,%5,%6,%7}, {%8,%9}, {%0,%1,%2,%3};\n"
        : "+f"(c[0]), "+f"(c[1]), "+f"(c[2]), "+f"(c[3])
        : "r"(a[0]), "r"(a[1]), "r"(a[2]), "r"(a[3]), "r"(b[0]), "r"(b[1]));
}
__device__ __forceinline__ void mma_f16(float* c, const uint32_t* a, const uint32_t* b) {
    asm volatile(
        "mma.sync.aligned.m16n8k16.row.col.f32.f16.f16.f32 "
        "{%0,%1,%2,%3}, {%4,%5,%6,%7}, {%8,%9}, {%0,%1,%2,%3};\n"
        : "+f"(c[0]), "+f"(c[1]), "+f"(c[2]), "+f"(c[3])
        : "r"(a[0]), "r"(a[1]), "r"(a[2]), "r"(a[3]), "r"(b[0]), "r"(b[1]));
}
__device__ __forceinline__ void mma_e4(float* c, const uint32_t* a, const uint32_t* b) {
    asm volatile(
        "mma.sync.aligned.m16n8k32.row.col.f32.e4m3.e4m3.f32 "
        "{%0,%1,%2,%3}, {%4,%5,%6,%7}, {%8,%9}, {%0,%1,%2,%3};\n"
        : "+f"(c[0]), "+f"(c[1]), "+f"(c[2]), "+f"(c[3])
        : "r"(a[0]), "r"(a[1]), "r"(a[2]), "r"(a[3]), "r"(b[0]), "r"(b[1]));
}
__device__ __forceinline__ void mma_tf32(float* c, const uint32_t* a, const uint32_t* b) {
    asm volatile(
        "mma.sync.aligned.m16n8k8.row.col.f32.tf32.tf32.f32 "
        "{%0,%1,%2,%3}, {%4,%5,%6,%7}, {%8,%9}, {%0,%1,%2,%3};\n"
        : "+f"(c[0]), "+f"(c[1]), "+f"(c[2]), "+f"(c[3])
        : "r"(a[0]), "r"(a[1]), "r"(a[2]), "r"(a[3]), "r"(b[0]), "r"(b[1]));
}
__device__ __forceinline__ void ldsm4(uint32_t& r0, uint32_t& r1, uint32_t& r2, uint32_t& r3,
                                      uint32_t addr) {
    asm volatile("ldmatrix.sync.aligned.m8n8.x4.shared.b16 {%0,%1,%2,%3}, [%4];\n"
                 : "=r"(r0), "=r"(r1), "=r"(r2), "=r"(r3) : "r"(addr));
}
__device__ __forceinline__ uint32_t ex2h2(float lo, float hi) {
    uint32_t h, d;
    asm("cvt.rn.f16x2.f32 %0, %1, %2;\n" : "=r"(h) : "f"(hi), "f"(lo));
    asm("ex2.approx.f16x2 %0, %1;\n" : "=r"(d) : "r"(h));
    return d;
}
__device__ __forceinline__ uint16_t pack_e4(float lo, float hi) {
    uint16_t u;
    asm("cvt.rn.satfinite.e4m3x2.f32 %0, %1, %2;\n" : "=h"(u) : "f"(hi), "f"(lo));
    return u;
}
__device__ __forceinline__ void cp16(uint32_t dst, const void* src) {
    asm volatile("cp.async.cg.shared.global [%0], [%1], 16;\n" :: "r"(dst), "l"(src));
}
__device__ __forceinline__ void cp16z(uint32_t dst, const void* src, int bytes) {
    asm volatile("cp.async.cg.shared.global [%0], [%1], 16, %2;\n" :: "r"(dst), "l"(src), "r"(bytes));
}
__device__ __forceinline__ void cp_commit() { asm volatile("cp.async.commit_group;\n"); }
__device__ __forceinline__ void cp_wait0()  { asm volatile("cp.async.wait_group 0;\n"); }

// swizzled 16B-chunk address: 8 chunks (128B) per smem row
__device__ __forceinline__ uint32_t swz(uint32_t base, int row, int c) {
    return base + (uint32_t)((row * 8 + (c ^ (row & 7))) << 4);
}

// ---------------- weight pre-conversion ------------------------------------
struct WPtrs { const float* p[8]; };
__global__ void wcvt_kernel(WPtrs w, __nv_bfloat16* __restrict__ dh, float* __restrict__ df) {
    int mat = blockIdx.y;
    const float* src;
    if (mat < 18) src = w.p[mat/3] + (size_t)(mat%3) * N2;
    else          src = w.p[6 + (mat - 18)];
    int i = (blockIdx.x * 256 + threadIdx.x) * 4;
    float4 v = *(const float4*)(src + i);
    if (mat < 18) {
        __nv_bfloat162* d = (__nv_bfloat162*)(dh + (size_t)mat * N2 + i);
        d[0] = __floats2bfloat162_rn(v.x, v.y);
        d[1] = __floats2bfloat162_rn(v.z, v.w);
    } else {
        float4 o;
        o.x = f2tff(v.x); o.y = f2tff(v.y); o.z = f2tff(v.z); o.w = f2tff(v.w);
        *(float4*)(df + (size_t)(mat - 18) * N2 + i) = o;
    }
}

// ---------------- tokenize --------------------------------------------------
__global__ void tok_kernel(const float* __restrict__ x1, float* __restrict__ t1o,
                           __nv_bfloat16* __restrict__ th1o,
                           const float* __restrict__ x2, float* __restrict__ t2o,
                           __nv_bfloat16* __restrict__ th2o) {
    __shared__ float tile[32][33];
    int z = blockIdx.z;
    int b = z >> 1, st = z & 1;
    const float* x = st ? x2 : x1;
    float* t = st ? t2o : t1o;
    __nv_bfloat16* th = st ? th2o : th1o;
    int n0 = blockIdx.x * 32, c0 = blockIdx.y * 32;
    int nx = n0 + threadIdx.x;
    #pragma unroll
    for (int i = 0; i < 32; i += 8) {
        int c = c0 + threadIdx.y + i;
        tile[threadIdx.y + i][threadIdx.x] = x[((size_t)b*NC + c)*NT + nx];
    }
    __syncthreads();
    int cx = c0 + threadIdx.x;
    #pragma unroll
    for (int i = 0; i < 32; i += 8) {
        int n = n0 + threadIdx.y + i;
        float v = tile[threadIdx.x][threadIdx.y + i];
        size_t off = ((size_t)b*NT + n)*NC + cx;
        t[off]  = v;
        th[off] = __float2bfloat16_rn(v);
    }
}

// ---------------- LayerNorm: warp-per-row -----------------------------------
__global__ __launch_bounds__(256)
void ln_kernel(const float* __restrict__ tA, const float* __restrict__ gA,
               const float* __restrict__ bA, __nv_bfloat16* __restrict__ oA,
               const float* __restrict__ tB, const float* __restrict__ gB,
               const float* __restrict__ bB, __nv_bfloat16* __restrict__ oB) {
    const float* t = blockIdx.y ? tB : tA;
    const float* gamma = blockIdx.y ? gB : gA;
    const float* beta  = blockIdx.y ? bB : bA;
    __nv_bfloat16* out = blockIdx.y ? oB : oA;

    int row  = blockIdx.x * 8 + (threadIdx.x >> 5);
    int lane = threadIdx.x & 31;

    const float4* x4 = (const float4*)(t + (size_t)row * NC);
    float4 v[4];
    float s = 0.0f, s2 = 0.0f;
    #pragma unroll
    for (int j = 0; j < 4; j++) {
        v[j] = x4[j*32 + lane];
        s  += v[j].x + v[j].y + v[j].z + v[j].w;
        s2 += v[j].x*v[j].x + v[j].y*v[j].y + v[j].z*v[j].z + v[j].w*v[j].w;
    }
    #pragma unroll
    for (int o = 16; o > 0; o >>= 1) {
        s  += __shfl_xor_sync(0xffffffffu, s,  o);
        s2 += __shfl_xor_sync(0xffffffffu, s2, o);
    }
    float mean = s * (1.0f / NC);
    float var  = s2 * (1.0f / NC) - mean * mean;
    float rstd = rsqrtf(var + 1e-5f);

    uint2* o8 = (uint2*)(out + (size_t)row * NC);
    #pragma unroll
    for (int j = 0; j < 4; j++) {
        float4 g4 = ((const float4*)gamma)[j*32 + lane];
        float4 b4 = ((const float4*)beta )[j*32 + lane];
        __nv_bfloat162 lo = __floats2bfloat162_rn((v[j].x - mean)*rstd*g4.x + b4.x,
                                                  (v[j].y - mean)*rstd*g4.y + b4.y);
        __nv_bfloat162 hi = __floats2bfloat162_rn((v[j].z - mean)*rstd*g4.z + b4.z,
                                                  (v[j].w - mean)*rstd*g4.w + b4.w);
        uint2 u;
        u.x = *(uint32_t*)&lo;
        u.y = *(uint32_t*)&hi;
        o8[j*32 + lane] = u;
    }
}

// ---------------- merged bf16 proj GEMM (2-stage pipeline) ------------------
// mode 0: Y e4m3 row-major, (acc+bias)*scale   (Q and K projections)
// mode 1: Y half, V^T store [b][c][tok], acc+bias
struct PArg {
    const __nv_bfloat16 *A, *W;
    const float *bias;
    void *Y;
    float scale;
    int mode;
};
struct PArgs { PArg op[6]; };

static constexpr int PROJ_SMEM_BYTES = 65536;

__global__ __launch_bounds__(256, 2)
void gemm_proj(PArgs pa) {
    constexpr int BM = 128, BN = 128, BK = 64, NIT = NC / BK;   // 8
    const PArg p = pa.op[blockIdx.z];
    extern __shared__ char smc[];
    const uint32_t sb = (uint32_t)__cvta_generic_to_shared(smc);
    const int tid = threadIdx.x, lane = tid & 31, warp = tid >> 5;
    const int g = lane >> 2, tg = lane & 3;
    const int wm = warp >> 2, wn = warp & 3;
    const int m0 = blockIdx.y * BM, n0 = blockIdx.x * BN;
    const __nv_bfloat16* X = p.A;
    const __nv_bfloat16* W = p.W;

    float acc[4][4][4] = {};

    auto issue = [&](int st, int k0) {
        uint32_t aB = sb + (uint32_t)st * 16384u;
        uint32_t bB = sb + 32768u + (uint32_t)st * 16384u;
        #pragma unroll
        for (int i = 0; i < 4; i++) {
            int idx = tid + i*256;
            int r = idx >> 3, c = idx & 7;
            cp16(swz(aB, r, c), X + (size_t)(m0 + r)*NC + k0 + c*8);
        }
        #pragma unroll
        for (int i = 0; i < 4; i++) {
            int idx = tid + i*256;
            int r = idx >> 3, c = idx & 7;
            cp16(swz(bB, r, c), W + (size_t)(n0 + r)*NC + k0 + c*8);
        }
        cp_commit();
    };

    issue(0, 0);
    #pragma unroll 1
    for (int it = 0; it < NIT; ++it) {
        cp_wait0();
        __syncthreads();
        if (it + 1 < NIT) issue((it + 1) & 1, (it + 1)*BK);
        uint32_t aB = sb + (uint32_t)(it & 1) * 16384u;
        uint32_t bB = sb + 32768u + (uint32_t)(it & 1) * 16384u;
        #pragma unroll
        for (int j = 0; j < 4; j++) {
            uint32_t a[4][4], bf[4][2];
            #pragma unroll
            for (int mt = 0; mt < 4; mt++) {
                int row = wm*64 + mt*16 + (lane & 15);
                int c   = 2*j + (lane >> 4);
                ldsm4(a[mt][0], a[mt][1], a[mt][2], a[mt][3], swz(aB, row, c));
            }
            #pragma unroll
            for (int q = 0; q < 2; q++) {
                int row = wn*32 + q*16 + ((lane >> 4) << 3) + (lane & 7);
                int c   = 2*j + ((lane >> 3) & 1);
                uint32_t r0, r1, r2, r3;
                ldsm4(r0, r1, r2, r3, swz(bB, row, c));
                bf[q*2][0] = r0; bf[q*2][1] = r1;
                bf[q*2+1][0] = r2; bf[q*2+1][1] = r3;
            }
            #pragma unroll
            for (int mt = 0; mt < 4; mt++)
                #pragma unroll
                for (int nt = 0; nt < 4; nt++)
                    mma_bf16(acc[mt][nt], a[mt], bf[nt]);
        }
    }

    if (p.mode == 0) {
        uint8_t* Y = (uint8_t*)p.Y;
        float scale = p.scale;
        #pragma unroll
        for (int mt = 0; mt < 4; mt++) {
            #pragma unroll
            for (int nt = 0; nt < 4; nt++) {
                int r0 = m0 + wm*64 + mt*16 + g;
                int c0 = n0 + wn*32 + nt*8 + 2*tg;
                float b0 = p.bias[c0], b1 = p.bias[c0 + 1];
                *(uint16_t*)(Y + (size_t)r0*NC + c0) =
                    pack_e4((acc[mt][nt][0] + b0)*scale, (acc[mt][nt][1] + b1)*scale);
                *(uint16_t*)(Y + (size_t)(r0+8)*NC + c0) =
                    pack_e4((acc[mt][nt][2] + b0)*scale, (acc[mt][nt][3] + b1)*scale);
            }
        }
    } else {
        __half* Y = (__half*)p.Y;
        #pragma unroll
        for (int mt = 0; mt < 4; mt++) {
            #pragma unroll
            for (int nt = 0; nt < 4; nt++) {
                int r0 = m0 + wm*64 + mt*16 + g;
                int c0 = n0 + wn*32 + nt*8 + 2*tg;
                #pragma unroll
                for (int e = 0; e < 4; e++) {
                    int r = r0 + (e >> 1)*8;
                    int o = c0 + (e & 1);
                    int b = r / NT, n = r % NT;
                    Y[((size_t)b*NC + o)*NT + n] = __float2half_rn(acc[mt][nt][e] + p.bias[o]);
                }
            }
        }
    }
}

// ---------------- FlashAttention: fp8 QK (1 token/row layout), f16 PV -------
// Q8,K8: e4m3 [b][tok][NC] (Q pre-scaled by (1/8)*log2e).  Vt: f16 [b][c][tok].
// smem: Q @0 (128 rows x 128B = 16KB, data in chunks 0..3 swizzled),
//       K stage s @16384+s*8192 (64 rows x 128B), V stage s @32768+s*8192. 48KB.
struct AArgs {
    const uint8_t *Q[2], *K[2];
    const __half *Vt[2];
    float *T[2];
    __nv_bfloat16 *Th[2];
    float *Tf[2];
};

static constexpr int ATTN_SMEM_BYTES = 49152;

__global__ __launch_bounds__(256, 2)
void attn_bf(AArgs aa) {
    extern __shared__ char smc[];
    const uint32_t sb  = (uint32_t)__cvta_generic_to_shared(smc);
    const uint32_t sbQ = sb;
    const int z = blockIdx.z;
    const int b = z >> 1, st = z & 1;
    const uint8_t* Q8 = aa.Q[st];
    const uint8_t* K8 = aa.K[st];
    const __half*  Vt = aa.Vt[st];
    float* T = aa.T[st];
    __nv_bfloat16* Th = aa.Th[st];
    float* Tf = aa.Tf[st];

    const int q0 = blockIdx.x * 128;
    const int h  = blockIdx.y;
    const int tid = threadIdx.x;
    const int lane = tid & 31, warp = tid >> 5;
    const int g = lane >> 2, tg = lane & 3;
    const int wr = warp * 16;
    const size_t base  = ((size_t)b * NT) * NC + h * DH;   // bytes for fp8
    const size_t vbase = ((size_t)b * NC + h * DH) * NT;

    // Q tile: 128 token-rows x 4 chunks (64B data per row)
    #pragma unroll
    for (int i = 0; i < 2; i++) {
        int idx = tid + i*256;                   // 0..511
        int r = idx >> 2, c = idx & 3;
        int row = q0 + r;
        int ok = (row < NT) ? 16 : 0;
        if (row >= NT) row = NT - 1;
        cp16z(swz(sbQ, r, c), Q8 + base + (size_t)row*NC + c*16, ok);
    }
    auto issueKV = [&](int stg, int kt) {
        uint32_t kB = sb + 16384u + (uint32_t)stg*8192u;
        uint32_t vB = sb + 32768u + (uint32_t)stg*8192u;
        {   // K: 64 token-rows x 4 chunks = 256
            int r = tid >> 2, c = tid & 3;
            int krow = kt + r;
            int kok = (krow < NT) ? 16 : 0;
            if (krow >= NT) krow = NT - 1;
            cp16z(swz(kB, r, c), K8 + base + (size_t)krow*NC + c*16, kok);
        }
        #pragma unroll
        for (int i = 0; i < 2; i++) {            // V: 64 rows x 8 chunks (f16)
            int idx = tid + i*256;
            int r = idx >> 3, c = idx & 7;
            int vtok = kt + c*8;
            int vok = (vtok < NT) ? 16 : 0;
            if (vtok >= NT) vtok = NT - 8;
            cp16z(swz(vB, r, c), Vt + vbase + (size_t)r*NT + vtok, vok);
        }
        cp_commit();
    };
    issueKV(0, 0);

    uint32_t qf[2][4];                           // A-frags for 2 k32 chunks
    float o[8][4] = {};
    float lrow0 = 0.0f, lrow1 = 0.0f;            // per-thread; reduced in epilogue
    constexpr int NIT = (NT + 63) / 64;          // 25

    #pragma unroll 1
    for (int it = 0; it < NIT; ++it) {
        cp_wait0();
        __syncthreads();
        if (it == 0) {
            #pragma unroll
            for (int j = 0; j < 2; j++) {
                int row = wr + (lane & 15);
                int c   = 2*j + (lane >> 4);
                ldsm4(qf[j][0], qf[j][1], qf[j][2], qf[j][3], swz(sbQ, row, c));
            }
        }
        if (it + 1 < NIT) issueKV((it + 1) & 1, (it + 1)*64);

        const uint32_t kB = sb + 16384u + (uint32_t)((it & 1))*8192u;
        const uint32_t vB = sb + 32768u + (uint32_t)((it & 1))*8192u;
        const int kt = it * 64;

        // ---- S = Q K^T (fp8 e4m3 k32): one ldsm4 per 8-token tile gives
        //      both k-chunk B-frags (r0,r1 = k0..31 ; r2,r3 = k32..63)
        float s[8][4] = {};
        #pragma unroll
        for (int nt8 = 0; nt8 < 8; nt8++) {
            int row = nt8*8 + (lane & 7);
            int c   = lane >> 3;                 // 0..3
            uint32_t r0, r1, r2, r3;
            ldsm4(r0, r1, r2, r3, swz(kB, row, c));
            uint32_t f0[2] = {r0, r1}, f1[2] = {r2, r3};
            mma_e4(s[nt8], qf[0], f0);
            mma_e4(s[nt8], qf[1], f1);
        }

        if (kt + 64 > NT) {
            #pragma unroll
            for (int nt = 0; nt < 8; nt++) {
                int c0 = kt + nt*8 + 2*tg;
                if (c0     >= NT) { s[nt][0] = -1e30f; s[nt][2] = -1e30f; }
                if (c0 + 1 >= NT) { s[nt][1] = -1e30f; s[nt][3] = -1e30f; }
            }
        }

        // ---- softmax numerator (no running max; logits bounded)
        uint32_t pa[4][4];
        __half2 sh0 = __floats2half2_rn(0.0f, 0.0f);
        __half2 sh1 = __floats2half2_rn(0.0f, 0.0f);
        #pragma unroll
        for (int j = 0; j < 4; j++) {
            uint32_t a0 = ex2h2(s[2*j][0],   s[2*j][1]);
            uint32_t a1 = ex2h2(s[2*j][2],   s[2*j][3]);
            uint32_t a2 = ex2h2(s[2*j+1][0], s[2*j+1][1]);
            uint32_t a3 = ex2h2(s[2*j+1][2], s[2*j+1][3]);
            pa[j][0] = a0; pa[j][1] = a1; pa[j][2] = a2; pa[j][3] = a3;
            sh0 = __hadd2(sh0, __hadd2(*(__half2*)&a0, *(__half2*)&a2));
            sh1 = __hadd2(sh1, __hadd2(*(__half2*)&a1, *(__half2*)&a3));
        }
        float2 f0 = __half22float2(sh0);
        float2 f1 = __half22float2(sh1);
        lrow0 += f0.x + f0.y;
        lrow1 += f1.x + f1.y;

        // ---- O += P V (f16 mma; P frags straight from ex2 output)
        #pragma unroll
        for (int j = 0; j < 4; j++) {
            #pragma unroll
            for (int q = 0; q < 4; q++) {
                int row = q*16 + ((lane >> 4) << 3) + (lane & 7);
                int c   = 2*j + ((lane >> 3) & 1);
                uint32_t r0, r1, r2, r3;
                ldsm4(r0, r1, r2, r3, swz(vB, row, c));
                uint32_t f0v[2] = {r0, r1}, f1v[2] = {r2, r3};
                mma_f16(o[q*2    ], pa[j], f0v);
                mma_f16(o[q*2 + 1], pa[j], f1v);
            }
        }
    }

    // deferred cross-lane l reduction
    lrow0 += __shfl_xor_sync(0xffffffffu, lrow0, 1);
    lrow0 += __shfl_xor_sync(0xffffffffu, lrow0, 2);
    lrow1 += __shfl_xor_sync(0xffffffffu, lrow1, 1);
    lrow1 += __shfl_xor_sync(0xffffffffu, lrow1, 2);

    int r0 = q0 + wr + g, r1 = r0 + 8;
    float inv0 = 1.0f / lrow0, inv1 = 1.0f / lrow1;
    #pragma unroll
    for (int nt = 0; nt < 8; nt++) {
        int d = nt*8 + 2*tg;
        if (r0 < NT) {
            size_t off = base + (size_t)r0*NC + d;
            float n0 = T[off]     + o[nt][0] * inv0;
            float n1 = T[off + 1] + o[nt][1] * inv0;
            T[off] = n0;  T[off + 1] = n1;
            if (Th) *(__nv_bfloat162*)(Th + off) = __floats2bfloat162_rn(n0, n1);
            if (Tf) { Tf[off] = f2tff(n0); Tf[off + 1] = f2tff(n1); }
        }
        if (r1 < NT) {
            size_t off = base + (size_t)r1*NC + d;
            float n0 = T[off]     + o[nt][2] * inv1;
            float n1 = T[off + 1] + o[nt][3] * inv1;
            T[off] = n0;  T[off + 1] = n1;
            if (Th) *(__nv_bfloat162*)(Th + off) = __floats2bfloat162_rn(n0, n1);
            if (Tf) { Tf[off] = f2tff(n0); Tf[off + 1] = f2tff(n1); }
        }
    }
}

// ---------------- TF32 out-head GEMM ----------------------------------------
struct OArg { const float *X, *W, *bias, *bng, *bnb; float *Y; };
struct OArgs { OArg op[2]; };

__global__ __launch_bounds__(256)
void gemm_out(OArgs oa) {
    constexpr int BM = 128, BN = 64, BK = 32;
    const OArg p = oa.op[blockIdx.z];
    extern __shared__ float smem[];
    const uint32_t sb = (uint32_t)__cvta_generic_to_shared(smem);
    const int tid = threadIdx.x, lane = tid & 31, warp = tid >> 5;
    const int g = lane >> 2, tg = lane & 3;
    const int wm = warp >> 1, wn = warp & 1;
    const int m0 = blockIdx.y * BM, n0 = blockIdx.x * BN;
    const float* X = p.X;
    const float* W = p.W;

    float acc[2][4][4] = {};

    auto issue = [&](int st, int k0) {
        uint32_t aB = sb + (uint32_t)(st*BM*BK)*4u;
        uint32_t bB = sb + (uint32_t)(2*BM*BK + st*BN*BK)*4u;
        #pragma unroll
        for (int i = 0; i < 4; i++) {
            int idx = tid + i*256;
            int r = idx >> 3, c4 = idx & 7;
            cp16(aB + 4u*(r*32 + ((c4 ^ (r & 7)) << 2)),
                 X + (size_t)(m0 + r)*NC + k0 + c4*4);
        }
        #pragma unroll
        for (int i = 0; i < 2; i++) {
            int idx = tid + i*256;
            int r = idx >> 3, c4 = idx & 7;
            cp16(bB + 4u*(r*32 + ((c4 ^ (r & 7)) << 2)),
                 W + (size_t)(n0 + r)*NC + k0 + c4*4);
        }
        cp_commit();
    };

    issue(0, 0);
    #pragma unroll 1
    for (int it = 0; it < NC/BK; ++it) {
        cp_wait0();
        __syncthreads();
        if (it + 1 < NC/BK) issue((it + 1) & 1, (it + 1)*BK);
        const uint32_t aBase = sb + (uint32_t)((it & 1)*BM*BK)*4u;
        const uint32_t bBase = sb + (uint32_t)(2*BM*BK + (it & 1)*BN*BK)*4u;
        #pragma unroll
        for (int kk = 0; kk < BK; kk += 8) {
            const int c0 = kk >> 2;
            uint32_t a[2][4], b[4][2];
            #pragma unroll
            for (int mt = 0; mt < 2; mt++) {
                int row = wm*32 + mt*16 + (lane & 15);
                int c4  = c0 + (lane >> 4);
                ldsm4(a[mt][0], a[mt][1], a[mt][2], a[mt][3],
                      aBase + 4u*(row*32 + ((c4 ^ (row & 7)) << 2)));
            }
            #pragma unroll
            for (int pq = 0; pq < 2; pq++) {
                int row = wn*32 + ((pq*2 + ((lane >> 4) & 1)) << 3) + (lane & 7);
                int c4  = c0 + ((lane >> 3) & 1);
                ldsm4(b[pq*2][0], b[pq*2][1], b[pq*2+1][0], b[pq*2+1][1],
                      bBase + 4u*(row*32 + ((c4 ^ (row & 7)) << 2)));
            }
            #pragma unroll
            for (int mt = 0; mt < 2; mt++)
                #pragma unroll
                for (int nt = 0; nt < 4; nt++)
                    mma_tf32(acc[mt][nt], a[mt], b[nt]);
        }
    }

    const float bns = rsqrtf(1.0f + 1e-5f);
    #pragma unroll
    for (int mt = 0; mt < 2; mt++) {
        #pragma unroll
        for (int nt = 0; nt < 4; nt++) {
            int r0 = m0 + wm*32 + mt*16 + g;
            int c0 = n0 + wn*32 + nt*8 + 2*tg;
            #pragma unroll
            for (int e = 0; e < 4; e++) {
                int r = r0 + (e >> 1)*8;
                int oc = c0 + (e & 1);
                int b = r / NT, n = r % NT;
                float z = acc[mt][nt][e] + p.bias[oc];
                z = fmaxf(z, 0.0f) * bns;
                p.Y[((size_t)b*NC + oc)*NT + n] = z * p.bng[oc] + p.bnb[oc];
            }
        }
    }
}

// ---------------------------------------------------------------------------
extern "C" void kernel_launch(void* const* d_in, const int* in_sizes, int n_in,
                              void* d_out, int out_size) {
    const float* x1   = (const float*)d_in[0];
    const float* x2   = (const float*)d_in[1];
    const float* Wq1  = (const float*)d_in[2];
    const float* bq1  = (const float*)d_in[3];
    const float* Wk1  = (const float*)d_in[4];
    const float* bk1  = (const float*)d_in[5];
    const float* Wv1  = (const float*)d_in[6];
    const float* bv1  = (const float*)d_in[7];
    const float* ln1g = (const float*)d_in[8];
    const float* ln1b = (const float*)d_in[9];
    const float* Wq2  = (const float*)d_in[10];
    const float* bq2  = (const float*)d_in[11];
    const float* Wk2  = (const float*)d_in[12];
    const float* bk2  = (const float*)d_in[13];
    const float* Wv2  = (const float*)d_in[14];
    const float* bv2  = (const float*)d_in[15];
    const float* ln2g = (const float*)d_in[16];
    const float* ln2b = (const float*)d_in[17];
    const float* o1w  = (const float*)d_in[18];
    const float* o1b  = (const float*)d_in[19];
    const float* bn1g = (const float*)d_in[20];
    const float* bn1b = (const float*)d_in[21];
    const float* o2w  = (const float*)d_in[22];
    const float* o2b  = (const float*)d_in[23];
    const float* bn2g = (const float*)d_in[24];
    const float* bn2b = (const float*)d_in[25];
    float* out = (float*)d_out;

    float *t1, *t2, *t1f, *t2f, *wf;
    void *th1, *th2, *ln1h, *ln2h, *q1h, *k1h, *v1h, *q2h, *k2h, *v2h, *wh;
    cudaGetSymbolAddress((void**)&t1,  g_t1);
    cudaGetSymbolAddress((void**)&t2,  g_t2);
    cudaGetSymbolAddress((void**)&t1f, g_t1f);
    cudaGetSymbolAddress((void**)&t2f, g_t2f);
    cudaGetSymbolAddress(&th1,  g_th1);
    cudaGetSymbolAddress(&th2,  g_th2);
    cudaGetSymbolAddress(&ln1h, g_ln1h);
    cudaGetSymbolAddress(&ln2h, g_ln2h);
    cudaGetSymbolAddress(&q1h, g_q1h);
    cudaGetSymbolAddress(&k1h, g_k1h);
    cudaGetSymbolAddress(&v1h, g_v1h);
    cudaGetSymbolAddress(&q2h, g_q2h);
    cudaGetSymbolAddress(&k2h, g_k2h);
    cudaGetSymbolAddress(&v2h, g_v2h);
    cudaGetSymbolAddress(&wh,  g_wh);
    cudaGetSymbolAddress((void**)&wf, g_wf);
    __nv_bfloat16 *TH1 = (__nv_bfloat16*)th1, *TH2 = (__nv_bfloat16*)th2;
    __nv_bfloat16 *LN1 = (__nv_bfloat16*)ln1h, *LN2 = (__nv_bfloat16*)ln2h;
    __nv_bfloat16 *WH = (__nv_bfloat16*)wh;
    uint8_t *Q1 = (uint8_t*)q1h, *K1 = (uint8_t*)k1h;
    uint8_t *Q2 = (uint8_t*)q2h, *K2 = (uint8_t*)k2h;
    __half *V1 = (__half*)v1h, *V2 = (__half*)v2h;

    const int OUT_SMEM = 49152;
    cudaFuncSetAttribute(gemm_proj, cudaFuncAttributeMaxDynamicSharedMemorySize, PROJ_SMEM_BYTES);
    cudaFuncSetAttribute(gemm_out,  cudaFuncAttributeMaxDynamicSharedMemorySize, OUT_SMEM);
    cudaFuncSetAttribute(attn_bf,   cudaFuncAttributeMaxDynamicSharedMemorySize, ATTN_SMEM_BYTES);

    WPtrs wp;
    wp.p[0] = Wq1; wp.p[1] = Wk1; wp.p[2] = Wv1;
    wp.p[3] = Wq2; wp.p[4] = Wk2; wp.p[5] = Wv2;
    wp.p[6] = o1w; wp.p[7] = o2w;
    wcvt_kernel<<<dim3(N2/1024, 20), 256>>>(wp, WH, wf);

    dim3 tokGrid(NT/32, NC/32, 2*NB), tokBlk(32, 8);
    tok_kernel<<<tokGrid, tokBlk>>>(x1, t1, TH1, x2, t2, TH2);

    dim3 pGrid(NC/128, NM/128, 6);          // (4, 49, 6)
    dim3 aGrid((NT + 127)/128, NH, 2*NB);   // (13, 8, 8)
    dim3 oGrid(NC/64, NM/128, 2);           // (8, 49, 2)
    const float qs = 0.125f * LOG2E, one = 1.0f;

    for (int i = 0; i < 3; i++) {
        ln_kernel<<<dim3(NM/8, 2), 256>>>(t1, ln1g + i*NC, ln1b + i*NC, LN1,
                                          t2, ln2g + i*NC, ln2b + i*NC, LN2);
        PArgs pa;
        pa.op[0] = { LN1, WH + (size_t)(0*3 + i)*N2, bq1 + i*NC, Q1, qs,  0 };
        pa.op[1] = { TH2, WH + (size_t)(1*3 + i)*N2, bk1 + i*NC, K1, one, 0 };
        pa.op[2] = { TH2, WH + (size_t)(2*3 + i)*N2, bv1 + i*NC, V1, one, 1 };
        pa.op[3] = { LN2, WH + (size_t)(3*3 + i)*N2, bq2 + i*NC, Q2, qs,  0 };
        pa.op[4] = { TH1, WH + (size_t)(4*3 + i)*N2, bk2 + i*NC, K2, one, 0 };
        pa.op[5] = { TH1, WH + (size_t)(5*3 + i)*N2, bv2 + i*NC, V2, one, 1 };
        gemm_proj<<<pGrid, 256, PROJ_SMEM_BYTES>>>(pa);

        bool last = (i == 2);
        AArgs aa;
        aa.Q[0] = Q1;  aa.Q[1] = Q2;
        aa.K[0] = K1;  aa.K[1] = K2;
        aa.Vt[0] = V1; aa.Vt[1] = V2;
        aa.T[0] = t1;  aa.T[1] = t2;
        aa.Th[0] = last ? nullptr : TH1;  aa.Th[1] = last ? nullptr : TH2;
        aa.Tf[0] = last ? t1f : nullptr;  aa.Tf[1] = last ? t2f : nullptr;
        attn_bf<<<aGrid, 256, ATTN_SMEM_BYTES>>>(aa);
    }

    OArgs oa;
    oa.op[0] = { t1f, wf,      o1b, bn1g, bn1b, out };
    oa.op[1] = { t2f, wf + N2, o2b, bn2g, bn2b, out + (size_t)NB*NC*NT };
    gemm_out<<<oGrid, 256, OUT_SMEM>>>(oa);
}

// round 15
// speedup vs baseline: 1.0325x; 1.0325x over previous
#include <cuda_runtime.h>
#include <cuda_bf16.h>
#include <cuda_fp16.h>
#include <cstdint>

static constexpr int NB = 4, NT = 1568, NC = 512, NH = 8, DH = 64;
static constexpr int NM = NB * NT;   // 6272
static constexpr int N2 = NC * NC;   // 262144
static constexpr float LOG2E = 1.4426950408889634f;

// ---------------- scratch ---------------------------------------------------
__device__ float g_t1 [NB*NT*NC];
__device__ float g_t2 [NB*NT*NC];
__device__ float g_t1f[NB*NT*NC];
__device__ float g_t2f[NB*NT*NC];
__device__ float g_th1[NB*NT*NC/2];
__device__ float g_th2[NB*NT*NC/2];
__device__ float g_ln1h[NB*NT*NC/2];
__device__ float g_ln2h[NB*NT*NC/2];
__device__ float g_q1h[NB*NT*NC/2];
__device__ float g_k1h[NB*NT*NC/2];
__device__ float g_v1h[NB*NT*NC/2];   // V^T f16: [b][c][tok]
__device__ float g_q2h[NB*NT*NC/2];
__device__ float g_k2h[NB*NT*NC/2];
__device__ float g_v2h[NB*NT*NC/2];
__device__ float g_wh [18*N2/2];
__device__ float g_wf [2*N2];

// ---------------- helpers ---------------------------------------------------
__device__ __forceinline__ uint32_t f2tf(float f) {
    uint32_t u;
    asm("cvt.rna.tf32.f32 %0, %1;\n" : "=r"(u) : "f"(f));
    return u;
}
__device__ __forceinline__ float f2tff(float f) { return __uint_as_float(f2tf(f)); }

__device__ __forceinline__ void mma_bf16(float* c, const uint32_t* a, const uint32_t* b) {
    asm volatile(
        "mma.sync.aligned.m16n8k16.row.col.f32.bf16.bf16.f32 "
        "{%0,%1,%2,%3}, {%4,%5,%6,%7}, {%8,%9}, {%0,%1,%2,%3};\n"
        : "+f"(c[0]), "+f"(c[1]), "+f"(c[2]), "+f"(c[3])
        : "r"(a[0]), "r"(a[1]), "r"(a[2]), "r"(a[3]), "r"(b[0]), "r"(b[1]));
}
__device__ __forceinline__ void mma_f16(float* c, const uint32_t* a, const uint32_t* b) {
    asm volatile(
        "mma.sync.aligned.m16n8k16.row.col.f32.f16.f16.f32 "
        "{%0,%1,%2,%3}, {%4,%5,%6,%7}, {%8,%9}, {%0,%1,%2,%3};\n"
        : "+f"(c[0]), "+f"(c[1]), "+f"(c[2]), "+f"(c[3])
        : "r"(a[0]), "r"(a[1]), "r"(a[2]), "r"(a[3]), "r"(b[0]), "r"(b[1]));
}
__device__ __forceinline__ void mma_tf32(float* c, const uint32_t* a, const uint32_t* b) {
    asm volatile(
        "mma.sync.aligned.m16n8k8.row.col.f32.tf32.tf32.f32 "
        "{%0,%1,%2,%3}, {%4,%5,%6,%7}, {%8,%9}, {%0,%1,%2,%3};\n"
        : "+f"(c[0]), "+f"(c[1]), "+f"(c[2]), "+f"(c[3])
        : "r"(a[0]), "r"(a[1]), "r"(a[2]), "r"(a[3]), "r"(b[0]), "r"(b[1]));
}
__device__ __forceinline__ void ldsm4(uint32_t& r0, uint32_t& r1, uint32_t& r2, uint32_t& r3,
                                      uint32_t addr) {
    asm volatile("ldmatrix.sync.aligned.m8n8.x4.shared.b16 {%0,%1,%2,%3}, [%4];\n"
                 : "=r"(r0), "=r"(r1), "=r"(r2), "=r"(r3) : "r"(addr));
}
__device__ __forceinline__ uint32_t ex2h2(float lo, float hi) {
    uint32_t h, d;
    asm("cvt.rn.f16x2.f32 %0, %1, %2;\n" : "=r"(h) : "f"(hi), "f"(lo));
    asm("ex2.approx.f16x2 %0, %1;\n" : "=r"(d) : "r"(h));
    return d;
}
__device__ __forceinline__ void cp16(uint32_t dst, const void* src) {
    asm volatile("cp.async.cg.shared.global [%0], [%1], 16;\n" :: "r"(dst), "l"(src));
}
__device__ __forceinline__ void cp16z(uint32_t dst, const void* src, int bytes) {
    asm volatile("cp.async.cg.shared.global [%0], [%1], 16, %2;\n" :: "r"(dst), "l"(src), "r"(bytes));
}
__device__ __forceinline__ void cp_commit() { asm volatile("cp.async.commit_group;\n"); }
__device__ __forceinline__ void cp_wait0()  { asm volatile("cp.async.wait_group 0;\n"); }

__device__ __forceinline__ uint32_t swz(uint32_t base, int row, int c) {
    return base + (uint32_t)((row * 8 + (c ^ (row & 7))) << 4);
}

// ---------------- weight pre-conversion ------------------------------------
struct WPtrs { const float* p[8]; };
__global__ void wcvt_kernel(WPtrs w, __nv_bfloat16* __restrict__ dh, float* __restrict__ df) {
    int mat = blockIdx.y;
    const float* src;
    if (mat < 18) src = w.p[mat/3] + (size_t)(mat%3) * N2;
    else          src = w.p[6 + (mat - 18)];
    int i = (blockIdx.x * 256 + threadIdx.x) * 4;
    float4 v = *(const float4*)(src + i);
    if (mat < 18) {
        __nv_bfloat162* d = (__nv_bfloat162*)(dh + (size_t)mat * N2 + i);
        d[0] = __floats2bfloat162_rn(v.x, v.y);
        d[1] = __floats2bfloat162_rn(v.z, v.w);
    } else {
        float4 o;
        o.x = f2tff(v.x); o.y = f2tff(v.y); o.z = f2tff(v.z); o.w = f2tff(v.w);
        *(float4*)(df + (size_t)(mat - 18) * N2 + i) = o;
    }
}

// ---------------- tokenize --------------------------------------------------
__global__ void tok_kernel(const float* __restrict__ x1, float* __restrict__ t1o,
                           __nv_bfloat16* __restrict__ th1o,
                           const float* __restrict__ x2, float* __restrict__ t2o,
                           __nv_bfloat16* __restrict__ th2o) {
    __shared__ float tile[32][33];
    int z = blockIdx.z;
    int b = z >> 1, st = z & 1;
    const float* x = st ? x2 : x1;
    float* t = st ? t2o : t1o;
    __nv_bfloat16* th = st ? th2o : th1o;
    int n0 = blockIdx.x * 32, c0 = blockIdx.y * 32;
    int nx = n0 + threadIdx.x;
    #pragma unroll
    for (int i = 0; i < 32; i += 8) {
        int c = c0 + threadIdx.y + i;
        tile[threadIdx.y + i][threadIdx.x] = x[((size_t)b*NC + c)*NT + nx];
    }
    __syncthreads();
    int cx = c0 + threadIdx.x;
    #pragma unroll
    for (int i = 0; i < 32; i += 8) {
        int n = n0 + threadIdx.y + i;
        float v = tile[threadIdx.x][threadIdx.y + i];
        size_t off = ((size_t)b*NT + n)*NC + cx;
        t[off]  = v;
        th[off] = __float2bfloat16_rn(v);
    }
}

// ---------------- LayerNorm: warp-per-row -----------------------------------
__global__ __launch_bounds__(256)
void ln_kernel(const float* __restrict__ tA, const float* __restrict__ gA,
               const float* __restrict__ bA, __nv_bfloat16* __restrict__ oA,
               const float* __restrict__ tB, const float* __restrict__ gB,
               const float* __restrict__ bB, __nv_bfloat16* __restrict__ oB) {
    const float* t = blockIdx.y ? tB : tA;
    const float* gamma = blockIdx.y ? gB : gA;
    const float* beta  = blockIdx.y ? bB : bA;
    __nv_bfloat16* out = blockIdx.y ? oB : oA;

    int row  = blockIdx.x * 8 + (threadIdx.x >> 5);
    int lane = threadIdx.x & 31;

    const float4* x4 = (const float4*)(t + (size_t)row * NC);
    float4 v[4];
    float s = 0.0f, s2 = 0.0f;
    #pragma unroll
    for (int j = 0; j < 4; j++) {
        v[j] = x4[j*32 + lane];
        s  += v[j].x + v[j].y + v[j].z + v[j].w;
        s2 += v[j].x*v[j].x + v[j].y*v[j].y + v[j].z*v[j].z + v[j].w*v[j].w;
    }
    #pragma unroll
    for (int o = 16; o > 0; o >>= 1) {
        s  += __shfl_xor_sync(0xffffffffu, s,  o);
        s2 += __shfl_xor_sync(0xffffffffu, s2, o);
    }
    float mean = s * (1.0f / NC);
    float var  = s2 * (1.0f / NC) - mean * mean;
    float rstd = rsqrtf(var + 1e-5f);

    uint2* o8 = (uint2*)(out + (size_t)row * NC);
    #pragma unroll
    for (int j = 0; j < 4; j++) {
        float4 g4 = ((const float4*)gamma)[j*32 + lane];
        float4 b4 = ((const float4*)beta )[j*32 + lane];
        __nv_bfloat162 lo = __floats2bfloat162_rn((v[j].x - mean)*rstd*g4.x + b4.x,
                                                  (v[j].y - mean)*rstd*g4.y + b4.y);
        __nv_bfloat162 hi = __floats2bfloat162_rn((v[j].z - mean)*rstd*g4.z + b4.z,
                                                  (v[j].w - mean)*rstd*g4.w + b4.w);
        uint2 u;
        u.x = *(uint32_t*)&lo;
        u.y = *(uint32_t*)&hi;
        o8[j*32 + lane] = u;
    }
}

// ---------------- merged bf16 proj GEMM (2-stage pipeline) ------------------
struct PArg {
    const __nv_bfloat16 *A, *W;
    const float *bias;
    void *Y;
    float scale;
    int mode;
};
struct PArgs { PArg op[6]; };

static constexpr int PROJ_SMEM_BYTES = 65536;

__global__ __launch_bounds__(256, 2)
void gemm_proj(PArgs pa) {
    constexpr int BM = 128, BN = 128, BK = 64, NIT = NC / BK;   // 8
    const PArg p = pa.op[blockIdx.z];
    extern __shared__ char smc[];
    const uint32_t sb = (uint32_t)__cvta_generic_to_shared(smc);
    const int tid = threadIdx.x, lane = tid & 31, warp = tid >> 5;
    const int g = lane >> 2, tg = lane & 3;
    const int wm = warp >> 2, wn = warp & 3;
    const int m0 = blockIdx.y * BM, n0 = blockIdx.x * BN;
    const __nv_bfloat16* X = p.A;
    const __nv_bfloat16* W = p.W;

    float acc[4][4][4] = {};

    auto issue = [&](int st, int k0) {
        uint32_t aB = sb + (uint32_t)st * 16384u;
        uint32_t bB = sb + 32768u + (uint32_t)st * 16384u;
        #pragma unroll
        for (int i = 0; i < 4; i++) {
            int idx = tid + i*256;
            int r = idx >> 3, c = idx & 7;
            cp16(swz(aB, r, c), X + (size_t)(m0 + r)*NC + k0 + c*8);
        }
        #pragma unroll
        for (int i = 0; i < 4; i++) {
            int idx = tid + i*256;
            int r = idx >> 3, c = idx & 7;
            cp16(swz(bB, r, c), W + (size_t)(n0 + r)*NC + k0 + c*8);
        }
        cp_commit();
    };

    issue(0, 0);
    #pragma unroll 1
    for (int it = 0; it < NIT; ++it) {
        cp_wait0();
        __syncthreads();
        if (it + 1 < NIT) issue((it + 1) & 1, (it + 1)*BK);
        uint32_t aB = sb + (uint32_t)(it & 1) * 16384u;
        uint32_t bB = sb + 32768u + (uint32_t)(it & 1) * 16384u;
        #pragma unroll
        for (int j = 0; j < 4; j++) {
            uint32_t a[4][4], bf[4][2];
            #pragma unroll
            for (int mt = 0; mt < 4; mt++) {
                int row = wm*64 + mt*16 + (lane & 15);
                int c   = 2*j + (lane >> 4);
                ldsm4(a[mt][0], a[mt][1], a[mt][2], a[mt][3], swz(aB, row, c));
            }
            #pragma unroll
            for (int q = 0; q < 2; q++) {
                int row = wn*32 + q*16 + ((lane >> 4) << 3) + (lane & 7);
                int c   = 2*j + ((lane >> 3) & 1);
                uint32_t r0, r1, r2, r3;
                ldsm4(r0, r1, r2, r3, swz(bB, row, c));
                bf[q*2][0] = r0; bf[q*2][1] = r1;
                bf[q*2+1][0] = r2; bf[q*2+1][1] = r3;
            }
            #pragma unroll
            for (int mt = 0; mt < 4; mt++)
                #pragma unroll
                for (int nt = 0; nt < 4; nt++)
                    mma_bf16(acc[mt][nt], a[mt], bf[nt]);
        }
    }

    if (p.mode == 0) {
        __nv_bfloat16* Y = (__nv_bfloat16*)p.Y;
        float scale = p.scale;
        #pragma unroll
        for (int mt = 0; mt < 4; mt++) {
            #pragma unroll
            for (int nt = 0; nt < 4; nt++) {
                int r0 = m0 + wm*64 + mt*16 + g;
                int c0 = n0 + wn*32 + nt*8 + 2*tg;
                float b0 = p.bias[c0], b1 = p.bias[c0 + 1];
                *(__nv_bfloat162*)(Y + (size_t)r0*NC + c0) =
                    __floats2bfloat162_rn((acc[mt][nt][0] + b0)*scale, (acc[mt][nt][1] + b1)*scale);
                *(__nv_bfloat162*)(Y + (size_t)(r0+8)*NC + c0) =
                    __floats2bfloat162_rn((acc[mt][nt][2] + b0)*scale, (acc[mt][nt][3] + b1)*scale);
            }
        }
    } else {
        __half* Y = (__half*)p.Y;
        #pragma unroll
        for (int mt = 0; mt < 4; mt++) {
            #pragma unroll
            for (int nt = 0; nt < 4; nt++) {
                int r0 = m0 + wm*64 + mt*16 + g;
                int c0 = n0 + wn*32 + nt*8 + 2*tg;
                #pragma unroll
                for (int e = 0; e < 4; e++) {
                    int r = r0 + (e >> 1)*8;
                    int o = c0 + (e & 1);
                    int b = r / NT, n = r % NT;
                    Y[((size_t)b*NC + o)*NT + n] = __float2half_rn(acc[mt][nt][e] + p.bias[o]);
                }
            }
        }
    }
}

// ---------------- FlashAttention: no-max softmax, deferred l-reduction ------
struct AArgs {
    const __nv_bfloat16 *Q[2], *K[2];
    const __half *Vt[2];
    float *T[2];
    __nv_bfloat16 *Th[2];
    float *Tf[2];
};

static constexpr int ATTN_SMEM_BYTES = 49152;

__global__ __launch_bounds__(256, 2)
void attn_bf(AArgs aa) {
    extern __shared__ char smc[];
    const uint32_t sb  = (uint32_t)__cvta_generic_to_shared(smc);
    const uint32_t sbQ = sb;
    const int z = blockIdx.z;
    const int b = z >> 1, st = z & 1;
    const __nv_bfloat16* Q = aa.Q[st];
    const __nv_bfloat16* K = aa.K[st];
    const __half*       Vt = aa.Vt[st];
    float* T = aa.T[st];
    __nv_bfloat16* Th = aa.Th[st];
    float* Tf = aa.Tf[st];

    const int q0 = blockIdx.x * 128;
    const int h  = blockIdx.y;
    const int tid = threadIdx.x;
    const int lane = tid & 31, warp = tid >> 5;
    const int g = lane >> 2, tg = lane & 3;
    const int wr = warp * 16;
    const size_t base  = ((size_t)b * NT) * NC + h * DH;
    const size_t vbase = ((size_t)b * NC + h * DH) * NT;

    #pragma unroll
    for (int i = 0; i < 4; i++) {
        int idx = tid + i*256;
        int r = idx >> 3, c = idx & 7;
        int row = q0 + r;
        int ok = (row < NT) ? 16 : 0;
        if (row >= NT) row = NT - 1;
        cp16z(swz(sbQ, r, c), Q + base + (size_t)row*NC + c*8, ok);
    }
    auto issueKV = [&](int stg, int kt) {
        uint32_t kB = sb + 16384u + (uint32_t)stg*8192u;
        uint32_t vB = sb + 32768u + (uint32_t)stg*8192u;
        #pragma unroll
        for (int i = 0; i < 2; i++) {
            int idx = tid + i*256;
            int r = idx >> 3, c = idx & 7;
            int krow = kt + r;
            int kok = (krow < NT) ? 16 : 0;
            if (krow >= NT) krow = NT - 1;
            cp16z(swz(kB, r, c), K + base + (size_t)krow*NC + c*8, kok);
            int vtok = kt + c*8;
            int vok = (vtok < NT) ? 16 : 0;
            if (vtok >= NT) vtok = NT - 8;
            cp16z(swz(vB, r, c), Vt + vbase + (size_t)r*NT + vtok, vok);
        }
        cp_commit();
    };
    issueKV(0, 0);

    uint32_t qf[4][4];
    float o[8][4] = {};
    float lrow0 = 0.0f, lrow1 = 0.0f;
    constexpr int NIT = (NT + 63) / 64;            // 25

    #pragma unroll 1
    for (int it = 0; it < NIT; ++it) {
        cp_wait0();
        __syncthreads();
        if (it == 0) {
            #pragma unroll
            for (int j = 0; j < 4; j++) {
                int row = wr + (lane & 15);
                int c   = 2*j + (lane >> 4);
                ldsm4(qf[j][0], qf[j][1], qf[j][2], qf[j][3], swz(sbQ, row, c));
            }
        }
        if (it + 1 < NIT) issueKV((it + 1) & 1, (it + 1)*64);

        const uint32_t kB = sb + 16384u + (uint32_t)((it & 1))*8192u;
        const uint32_t vB = sb + 32768u + (uint32_t)((it & 1))*8192u;
        const int kt = it * 64;

        float s[8][4] = {};
        #pragma unroll
        for (int j = 0; j < 4; j++) {
            #pragma unroll
            for (int q = 0; q < 4; q++) {
                int row = q*16 + ((lane >> 4) << 3) + (lane & 7);
                int c   = 2*j + ((lane >> 3) & 1);
                uint32_t r0, r1, r2, r3;
                ldsm4(r0, r1, r2, r3, swz(kB, row, c));
                uint32_t f0[2] = {r0, r1}, f1[2] = {r2, r3};
                mma_bf16(s[q*2    ], qf[j], f0);
                mma_bf16(s[q*2 + 1], qf[j], f1);
            }
        }

        if (kt + 64 > NT) {
            #pragma unroll
            for (int nt = 0; nt < 8; nt++) {
                int c0 = kt + nt*8 + 2*tg;
                if (c0     >= NT) { s[nt][0] = -1e30f; s[nt][2] = -1e30f; }
                if (c0 + 1 >= NT) { s[nt][1] = -1e30f; s[nt][3] = -1e30f; }
            }
        }

        uint32_t pa[4][4];
        __half2 sh0 = __floats2half2_rn(0.0f, 0.0f);
        __half2 sh1 = __floats2half2_rn(0.0f, 0.0f);
        #pragma unroll
        for (int j = 0; j < 4; j++) {
            uint32_t a0 = ex2h2(s[2*j][0],   s[2*j][1]);
            uint32_t a1 = ex2h2(s[2*j][2],   s[2*j][3]);
            uint32_t a2 = ex2h2(s[2*j+1][0], s[2*j+1][1]);
            uint32_t a3 = ex2h2(s[2*j+1][2], s[2*j+1][3]);
            pa[j][0] = a0; pa[j][1] = a1; pa[j][2] = a2; pa[j][3] = a3;
            sh0 = __hadd2(sh0, __hadd2(*(__half2*)&a0, *(__half2*)&a2));
            sh1 = __hadd2(sh1, __hadd2(*(__half2*)&a1, *(__half2*)&a3));
        }
        float2 f0 = __half22float2(sh0);
        float2 f1 = __half22float2(sh1);
        lrow0 += f0.x + f0.y;
        lrow1 += f1.x + f1.y;

        #pragma unroll
        for (int j = 0; j < 4; j++) {
            #pragma unroll
            for (int q = 0; q < 4; q++) {
                int row = q*16 + ((lane >> 4) << 3) + (lane & 7);
                int c   = 2*j + ((lane >> 3) & 1);
                uint32_t r0, r1, r2, r3;
                ldsm4(r0, r1, r2, r3, swz(vB, row, c));
                uint32_t f0v[2] = {r0, r1}, f1v[2] = {r2, r3};
                mma_f16(o[q*2    ], pa[j], f0v);
                mma_f16(o[q*2 + 1], pa[j], f1v);
            }
        }
    }

    lrow0 += __shfl_xor_sync(0xffffffffu, lrow0, 1);
    lrow0 += __shfl_xor_sync(0xffffffffu, lrow0, 2);
    lrow1 += __shfl_xor_sync(0xffffffffu, lrow1, 1);
    lrow1 += __shfl_xor_sync(0xffffffffu, lrow1, 2);

    int r0 = q0 + wr + g, r1 = r0 + 8;
    float inv0 = 1.0f / lrow0, inv1 = 1.0f / lrow1;
    #pragma unroll
    for (int nt = 0; nt < 8; nt++) {
        int d = nt*8 + 2*tg;
        if (r0 < NT) {
            size_t off = base + (size_t)r0*NC + d;
            float n0 = T[off]     + o[nt][0] * inv0;
            float n1 = T[off + 1] + o[nt][1] * inv0;
            T[off] = n0;  T[off + 1] = n1;
            if (Th) *(__nv_bfloat162*)(Th + off) = __floats2bfloat162_rn(n0, n1);
            if (Tf) { Tf[off] = f2tff(n0); Tf[off + 1] = f2tff(n1); }
        }
        if (r1 < NT) {
            size_t off = base + (size_t)r1*NC + d;
            float n0 = T[off]     + o[nt][2] * inv1;
            float n1 = T[off + 1] + o[nt][3] * inv1;
            T[off] = n0;  T[off + 1] = n1;
            if (Th) *(__nv_bfloat162*)(Th + off) = __floats2bfloat162_rn(n0, n1);
            if (Tf) { Tf[off] = f2tff(n0); Tf[off + 1] = f2tff(n1); }
        }
    }
}

// ---------------- TF32 out-head GEMM ----------------------------------------
struct OArg { const float *X, *W, *bias, *bng, *bnb; float *Y; };
struct OArgs { OArg op[2]; };

__global__ __launch_bounds__(256)
void gemm_out(OArgs oa) {
    constexpr int BM = 128, BN = 64, BK = 32;
    const OArg p = oa.op[blockIdx.z];
    extern __shared__ float smem[];
    const uint32_t sb = (uint32_t)__cvta_generic_to_shared(smem);
    const int tid = threadIdx.x, lane = tid & 31, warp = tid >> 5;
    const int g = lane >> 2, tg = lane & 3;
    const int wm = warp >> 1, wn = warp & 1;
    const int m0 = blockIdx.y * BM, n0 = blockIdx.x * BN;
    const float* X = p.X;
    const float* W = p.W;

    float acc[2][4][4] = {};

    auto issue = [&](int st, int k0) {
        uint32_t aB = sb + (uint32_t)(st*BM*BK)*4u;
        uint32_t bB = sb + (uint32_t)(2*BM*BK + st*BN*BK)*4u;
        #pragma unroll
        for (int i = 0; i < 4; i++) {
            int idx = tid + i*256;
            int r = idx >> 3, c4 = idx & 7;
            cp16(aB + 4u*(r*32 + ((c4 ^ (r & 7)) << 2)),
                 X + (size_t)(m0 + r)*NC + k0 + c4*4);
        }
        #pragma unroll
        for (int i = 0; i < 2; i++) {
            int idx = tid + i*256;
            int r = idx >> 3, c4 = idx & 7;
            cp16(bB + 4u*(r*32 + ((c4 ^ (r & 7)) << 2)),
                 W + (size_t)(n0 + r)*NC + k0 + c4*4);
        }
        cp_commit();
    };

    issue(0, 0);
    #pragma unroll 1
    for (int it = 0; it < NC/BK; ++it) {
        cp_wait0();
        __syncthreads();
        if (it + 1 < NC/BK) issue((it + 1) & 1, (it + 1)*BK);
        const uint32_t aBase = sb + (uint32_t)((it & 1)*BM*BK)*4u;
        const uint32_t bBase = sb + (uint32_t)(2*BM*BK + (it & 1)*BN*BK)*4u;
        #pragma unroll
        for (int kk = 0; kk < BK; kk += 8) {
            const int c0 = kk >> 2;
            uint32_t a[2][4], b[4][2];
            #pragma unroll
            for (int mt = 0; mt < 2; mt++) {
                int row = wm*32 + mt*16 + (lane & 15);
                int c4  = c0 + (lane >> 4);
                ldsm4(a[mt][0], a[mt][1], a[mt][2], a[mt][3],
                      aBase + 4u*(row*32 + ((c4 ^ (row & 7)) << 2)));
            }
            #pragma unroll
            for (int pq = 0; pq < 2; pq++) {
                int row = wn*32 + ((pq*2 + ((lane >> 4) & 1)) << 3) + (lane & 7);
                int c4  = c0 + ((lane >> 3) & 1);
                ldsm4(b[pq*2][0], b[pq*2][1], b[pq*2+1][0], b[pq*2+1][1],
                      bBase + 4u*(row*32 + ((c4 ^ (row & 7)) << 2)));
            }
            #pragma unroll
            for (int mt = 0; mt < 2; mt++)
                #pragma unroll
                for (int nt = 0; nt < 4; nt++)
                    mma_tf32(acc[mt][nt], a[mt], b[nt]);
        }
    }

    const float bns = rsqrtf(1.0f + 1e-5f);
    #pragma unroll
    for (int mt = 0; mt < 2; mt++) {
        #pragma unroll
        for (int nt = 0; nt < 4; nt++) {
            int r0 = m0 + wm*32 + mt*16 + g;
            int c0 = n0 + wn*32 + nt*8 + 2*tg;
            #pragma unroll
            for (int e = 0; e < 4; e++) {
                int r = r0 + (e >> 1)*8;
                int oc = c0 + (e & 1);
                int b = r / NT, n = r % NT;
                float z = acc[mt][nt][e] + p.bias[oc];
                z = fmaxf(z, 0.0f) * bns;
                p.Y[((size_t)b*NC + oc)*NT + n] = z * p.bng[oc] + p.bnb[oc];
            }
        }
    }
}

// ---------------------------------------------------------------------------
extern "C" void kernel_launch(void* const* d_in, const int* in_sizes, int n_in,
                              void* d_out, int out_size) {
    const float* x1   = (const float*)d_in[0];
    const float* x2   = (const float*)d_in[1];
    const float* Wq1  = (const float*)d_in[2];
    const float* bq1  = (const float*)d_in[3];
    const float* Wk1  = (const float*)d_in[4];
    const float* bk1  = (const float*)d_in[5];
    const float* Wv1  = (const float*)d_in[6];
    const float* bv1  = (const float*)d_in[7];
    const float* ln1g = (const float*)d_in[8];
    const float* ln1b = (const float*)d_in[9];
    const float* Wq2  = (const float*)d_in[10];
    const float* bq2  = (const float*)d_in[11];
    const float* Wk2  = (const float*)d_in[12];
    const float* bk2  = (const float*)d_in[13];
    const float* Wv2  = (const float*)d_in[14];
    const float* bv2  = (const float*)d_in[15];
    const float* ln2g = (const float*)d_in[16];
    const float* ln2b = (const float*)d_in[17];
    const float* o1w  = (const float*)d_in[18];
    const float* o1b  = (const float*)d_in[19];
    const float* bn1g = (const float*)d_in[20];
    const float* bn1b = (const float*)d_in[21];
    const float* o2w  = (const float*)d_in[22];
    const float* o2b  = (const float*)d_in[23];
    const float* bn2g = (const float*)d_in[24];
    const float* bn2b = (const float*)d_in[25];
    float* out = (float*)d_out;

    float *t1, *t2, *t1f, *t2f, *wf;
    void *th1, *th2, *ln1h, *ln2h, *q1h, *k1h, *v1h, *q2h, *k2h, *v2h, *wh;
    cudaGetSymbolAddress((void**)&t1,  g_t1);
    cudaGetSymbolAddress((void**)&t2,  g_t2);
    cudaGetSymbolAddress((void**)&t1f, g_t1f);
    cudaGetSymbolAddress((void**)&t2f, g_t2f);
    cudaGetSymbolAddress(&th1,  g_th1);
    cudaGetSymbolAddress(&th2,  g_th2);
    cudaGetSymbolAddress(&ln1h, g_ln1h);
    cudaGetSymbolAddress(&ln2h, g_ln2h);
    cudaGetSymbolAddress(&q1h, g_q1h);
    cudaGetSymbolAddress(&k1h, g_k1h);
    cudaGetSymbolAddress(&v1h, g_v1h);
    cudaGetSymbolAddress(&q2h, g_q2h);
    cudaGetSymbolAddress(&k2h, g_k2h);
    cudaGetSymbolAddress(&v2h, g_v2h);
    cudaGetSymbolAddress(&wh,  g_wh);
    cudaGetSymbolAddress((void**)&wf, g_wf);
    __nv_bfloat16 *TH1 = (__nv_bfloat16*)th1, *TH2 = (__nv_bfloat16*)th2;
    __nv_bfloat16 *LN1 = (__nv_bfloat16*)ln1h, *LN2 = (__nv_bfloat16*)ln2h;
    __nv_bfloat16 *WH = (__nv_bfloat16*)wh;
    __nv_bfloat16 *Q1 = (__nv_bfloat16*)q1h, *K1 = (__nv_bfloat16*)k1h;
    __nv_bfloat16 *Q2 = (__nv_bfloat16*)q2h, *K2 = (__nv_bfloat16*)k2h;
    __half *V1 = (__half*)v1h, *V2 = (__half*)v2h;

    const int OUT_SMEM = 49152;
    cudaFuncSetAttribute(gemm_proj, cudaFuncAttributeMaxDynamicSharedMemorySize, PROJ_SMEM_BYTES);
    cudaFuncSetAttribute(gemm_out,  cudaFuncAttributeMaxDynamicSharedMemorySize, OUT_SMEM);
    cudaFuncSetAttribute(attn_bf,   cudaFuncAttributeMaxDynamicSharedMemorySize, ATTN_SMEM_BYTES);

    WPtrs wp;
    wp.p[0] = Wq1; wp.p[1] = Wk1; wp.p[2] = Wv1;
    wp.p[3] = Wq2; wp.p[4] = Wk2; wp.p[5] = Wv2;
    wp.p[6] = o1w; wp.p[7] = o2w;
    wcvt_kernel<<<dim3(N2/1024, 20), 256>>>(wp, WH, wf);

    dim3 tokGrid(NT/32, NC/32, 2*NB), tokBlk(32, 8);
    tok_kernel<<<tokGrid, tokBlk>>>(x1, t1, TH1, x2, t2, TH2);

    dim3 pGrid(NC/128, NM/128, 6);          // (4, 49, 6)
    dim3 aGrid((NT + 127)/128, NH, 2*NB);   // (13, 8, 8)
    dim3 oGrid(NC/64, NM/128, 2);           // (8, 49, 2)
    const float qs = 0.125f * LOG2E, one = 1.0f;

    for (int i = 0; i < 3; i++) {
        ln_kernel<<<dim3(NM/8, 2), 256>>>(t1, ln1g + i*NC, ln1b + i*NC, LN1,
                                          t2, ln2g + i*NC, ln2b + i*NC, LN2);
        PArgs pa;
        pa.op[0] = { LN1, WH + (size_t)(0*3 + i)*N2, bq1 + i*NC, Q1, qs,  0 };
        pa.op[1] = { TH2, WH + (size_t)(1*3 + i)*N2, bk1 + i*NC, K1, one, 0 };
        pa.op[2] = { TH2, WH + (size_t)(2*3 + i)*N2, bv1 + i*NC, V1, one, 1 };
        pa.op[3] = { LN2, WH + (size_t)(3*3 + i)*N2, bq2 + i*NC, Q2, qs,  0 };
        pa.op[4] = { TH1, WH + (size_t)(4*3 + i)*N2, bk2 + i*NC, K2, one, 0 };
        pa.op[5] = { TH1, WH + (size_t)(5*3 + i)*N2, bv2 + i*NC, V2, one, 1 };
        gemm_proj<<<pGrid, 256, PROJ_SMEM_BYTES>>>(pa);

        bool last = (i == 2);
        AArgs aa;
        aa.Q[0] = Q1;  aa.Q[1] = Q2;
        aa.K[0] = K1;  aa.K[1] = K2;
        aa.Vt[0] = V1; aa.Vt[1] = V2;
        aa.T[0] = t1;  aa.T[1] = t2;
        aa.Th[0] = last ? nullptr : TH1;  aa.Th[1] = last ? nullptr : TH2;
        aa.Tf[0] = last ? t1f : nullptr;  aa.Tf[1] = last ? t2f : nullptr;
        attn_bf<<<aGrid, 256, ATTN_SMEM_BYTES>>>(aa);
    }

    OArgs oa;
    oa.op[0] = { t1f, wf,      o1b, bn1g, bn1b, out };
    oa.op[1] = { t2f, wf + N2, o2b, bn2g, bn2b, out + (size_t)NB*NC*NT };
    gemm_out<<<oGrid, 256, OUT_SMEM>>>(oa);
}

// round 16
// speedup vs baseline: 1.0366x; 1.0039x over previous
#include <cuda_runtime.h>
#include <cuda_bf16.h>
#include <cuda_fp16.h>
#include <cstdint>

static constexpr int NB = 4, NT = 1568, NC = 512, NH = 8, DH = 64;
static constexpr int NM = NB * NT;   // 6272
static constexpr int N2 = NC * NC;   // 262144
static constexpr float LOG2E = 1.4426950408889634f;

// ---------------- scratch ---------------------------------------------------
__device__ float g_t1 [NB*NT*NC];
__device__ float g_t2 [NB*NT*NC];
__device__ float g_t1f[NB*NT*NC];
__device__ float g_t2f[NB*NT*NC];
__device__ float g_th1[NB*NT*NC/2];
__device__ float g_th2[NB*NT*NC/2];
__device__ float g_ln1h[NB*NT*NC/2];
__device__ float g_ln2h[NB*NT*NC/2];
__device__ float g_q1h[NB*NT*NC/2];
__device__ float g_k1h[NB*NT*NC/2];
__device__ float g_v1h[NB*NT*NC/2];   // V^T f16: [b][c][tok]
__device__ float g_q2h[NB*NT*NC/2];
__device__ float g_k2h[NB*NT*NC/2];
__device__ float g_v2h[NB*NT*NC/2];
__device__ float g_wh [18*N2/2];
__device__ float g_wf [2*N2];

// ---------------- helpers ---------------------------------------------------
__device__ __forceinline__ uint32_t f2tf(float f) {
    uint32_t u;
    asm("cvt.rna.tf32.f32 %0, %1;\n" : "=r"(u) : "f"(f));
    return u;
}
__device__ __forceinline__ float f2tff(float f) { return __uint_as_float(f2tf(f)); }

__device__ __forceinline__ void mma_bf16(float* c, const uint32_t* a, const uint32_t* b) {
    asm volatile(
        "mma.sync.aligned.m16n8k16.row.col.f32.bf16.bf16.f32 "
        "{%0,%1,%2,%3}, {%4,%5,%6,%7}, {%8,%9}, {%0,%1,%2,%3};\n"
        : "+f"(c[0]), "+f"(c[1]), "+f"(c[2]), "+f"(c[3])
        : "r"(a[0]), "r"(a[1]), "r"(a[2]), "r"(a[3]), "r"(b[0]), "r"(b[1]));
}
__device__ __forceinline__ void mma_f16(float* c, const uint32_t* a, const uint32_t* b) {
    asm volatile(
        "mma.sync.aligned.m16n8k16.row.col.f32.f16.f16.f32 "
        "{%0,%1,%2,%3}, {%4,%5,%6,%7}, {%8,%9}, {%0,%1,%2,%3};\n"
        : "+f"(c[0]), "+f"(c[1]), "+f"(c[2]), "+f"(c[3])
        : "r"(a[0]), "r"(a[1]), "r"(a[2]), "r"(a[3]), "r"(b[0]), "r"(b[1]));
}
__device__ __forceinline__ void mma_tf32(float* c, const uint32_t* a, const uint32_t* b) {
    asm volatile(
        "mma.sync.aligned.m16n8k8.row.col.f32.tf32.tf32.f32 "
        "{%0,%1,%2,%3}, {%4,%5,%6,%7}, {%8,%9}, {%0,%1,%2,%3};\n"
        : "+f"(c[0]), "+f"(c[1]), "+f"(c[2]), "+f"(c[3])
        : "r"(a[0]), "r"(a[1]), "r"(a[2]), "r"(a[3]), "r"(b[0]), "r"(b[1]));
}
__device__ __forceinline__ void ldsm4(uint32_t& r0, uint32_t& r1, uint32_t& r2, uint32_t& r3,
                                      uint32_t addr) {
    asm volatile("ldmatrix.sync.aligned.m8n8.x4.shared.b16 {%0,%1,%2,%3}, [%4];\n"
                 : "=r"(r0), "=r"(r1), "=r"(r2), "=r"(r3) : "r"(addr));
}
__device__ __forceinline__ uint32_t ex2h2(float lo, float hi) {
    uint32_t h, d;
    asm("cvt.rn.f16x2.f32 %0, %1, %2;\n" : "=r"(h) : "f"(hi), "f"(lo));
    asm("ex2.approx.f16x2 %0, %1;\n" : "=r"(d) : "r"(h));
    return d;
}
__device__ __forceinline__ void cp16(uint32_t dst, const void* src) {
    asm volatile("cp.async.cg.shared.global [%0], [%1], 16;\n" :: "r"(dst), "l"(src));
}
__device__ __forceinline__ void cp16z(uint32_t dst, const void* src, int bytes) {
    asm volatile("cp.async.cg.shared.global [%0], [%1], 16, %2;\n" :: "r"(dst), "l"(src), "r"(bytes));
}
__device__ __forceinline__ void cp_commit() { asm volatile("cp.async.commit_group;\n"); }
__device__ __forceinline__ void cp_wait0()  { asm volatile("cp.async.wait_group 0;\n"); }

__device__ __forceinline__ uint32_t swz(uint32_t base, int row, int c) {
    return base + (uint32_t)((row * 8 + (c ^ (row & 7))) << 4);
}

// ---------------- weight pre-conversion ------------------------------------
struct WPtrs { const float* p[8]; };
__global__ void wcvt_kernel(WPtrs w, __nv_bfloat16* __restrict__ dh, float* __restrict__ df) {
    int mat = blockIdx.y;
    const float* src;
    if (mat < 18) src = w.p[mat/3] + (size_t)(mat%3) * N2;
    else          src = w.p[6 + (mat - 18)];
    int i = (blockIdx.x * 256 + threadIdx.x) * 4;
    float4 v = *(const float4*)(src + i);
    if (mat < 18) {
        __nv_bfloat162* d = (__nv_bfloat162*)(dh + (size_t)mat * N2 + i);
        d[0] = __floats2bfloat162_rn(v.x, v.y);
        d[1] = __floats2bfloat162_rn(v.z, v.w);
    } else {
        float4 o;
        o.x = f2tff(v.x); o.y = f2tff(v.y); o.z = f2tff(v.z); o.w = f2tff(v.w);
        *(float4*)(df + (size_t)(mat - 18) * N2 + i) = o;
    }
}

// ---------------- tokenize --------------------------------------------------
__global__ void tok_kernel(const float* __restrict__ x1, float* __restrict__ t1o,
                           __nv_bfloat16* __restrict__ th1o,
                           const float* __restrict__ x2, float* __restrict__ t2o,
                           __nv_bfloat16* __restrict__ th2o) {
    __shared__ float tile[32][33];
    int z = blockIdx.z;
    int b = z >> 1, st = z & 1;
    const float* x = st ? x2 : x1;
    float* t = st ? t2o : t1o;
    __nv_bfloat16* th = st ? th2o : th1o;
    int n0 = blockIdx.x * 32, c0 = blockIdx.y * 32;
    int nx = n0 + threadIdx.x;
    #pragma unroll
    for (int i = 0; i < 32; i += 8) {
        int c = c0 + threadIdx.y + i;
        tile[threadIdx.y + i][threadIdx.x] = x[((size_t)b*NC + c)*NT + nx];
    }
    __syncthreads();
    int cx = c0 + threadIdx.x;
    #pragma unroll
    for (int i = 0; i < 32; i += 8) {
        int n = n0 + threadIdx.y + i;
        float v = tile[threadIdx.x][threadIdx.y + i];
        size_t off = ((size_t)b*NT + n)*NC + cx;
        t[off]  = v;
        th[off] = __float2bfloat16_rn(v);
    }
}

// ---------------- LayerNorm: warp-per-row -----------------------------------
__global__ __launch_bounds__(256)
void ln_kernel(const float* __restrict__ tA, const float* __restrict__ gA,
               const float* __restrict__ bA, __nv_bfloat16* __restrict__ oA,
               const float* __restrict__ tB, const float* __restrict__ gB,
               const float* __restrict__ bB, __nv_bfloat16* __restrict__ oB) {
    const float* t = blockIdx.y ? tB : tA;
    const float* gamma = blockIdx.y ? gB : gA;
    const float* beta  = blockIdx.y ? bB : bA;
    __nv_bfloat16* out = blockIdx.y ? oB : oA;

    int row  = blockIdx.x * 8 + (threadIdx.x >> 5);
    int lane = threadIdx.x & 31;

    const float4* x4 = (const float4*)(t + (size_t)row * NC);
    float4 v[4];
    float s = 0.0f, s2 = 0.0f;
    #pragma unroll
    for (int j = 0; j < 4; j++) {
        v[j] = x4[j*32 + lane];
        s  += v[j].x + v[j].y + v[j].z + v[j].w;
        s2 += v[j].x*v[j].x + v[j].y*v[j].y + v[j].z*v[j].z + v[j].w*v[j].w;
    }
    #pragma unroll
    for (int o = 16; o > 0; o >>= 1) {
        s  += __shfl_xor_sync(0xffffffffu, s,  o);
        s2 += __shfl_xor_sync(0xffffffffu, s2, o);
    }
    float mean = s * (1.0f / NC);
    float var  = s2 * (1.0f / NC) - mean * mean;
    float rstd = rsqrtf(var + 1e-5f);

    uint2* o8 = (uint2*)(out + (size_t)row * NC);
    #pragma unroll
    for (int j = 0; j < 4; j++) {
        float4 g4 = ((const float4*)gamma)[j*32 + lane];
        float4 b4 = ((const float4*)beta )[j*32 + lane];
        __nv_bfloat162 lo = __floats2bfloat162_rn((v[j].x - mean)*rstd*g4.x + b4.x,
                                                  (v[j].y - mean)*rstd*g4.y + b4.y);
        __nv_bfloat162 hi = __floats2bfloat162_rn((v[j].z - mean)*rstd*g4.z + b4.z,
                                                  (v[j].w - mean)*rstd*g4.w + b4.w);
        uint2 u;
        u.x = *(uint32_t*)&lo;
        u.y = *(uint32_t*)&hi;
        o8[j*32 + lane] = u;
    }
}

// ---------------- merged bf16 proj GEMM (2-stage pipeline) ------------------
struct PArg {
    const __nv_bfloat16 *A, *W;
    const float *bias;
    void *Y;
    float scale;
    int mode;
};
struct PArgs { PArg op[6]; };

static constexpr int PROJ_SMEM_BYTES = 65536;

__global__ __launch_bounds__(256, 2)
void gemm_proj(PArgs pa) {
    constexpr int BM = 128, BN = 128, BK = 64, NIT = NC / BK;   // 8
    const PArg p = pa.op[blockIdx.z];
    extern __shared__ char smc[];
    const uint32_t sb = (uint32_t)__cvta_generic_to_shared(smc);
    const int tid = threadIdx.x, lane = tid & 31, warp = tid >> 5;
    const int g = lane >> 2, tg = lane & 3;
    const int wm = warp >> 2, wn = warp & 3;
    const int m0 = blockIdx.y * BM, n0 = blockIdx.x * BN;
    const __nv_bfloat16* X = p.A;
    const __nv_bfloat16* W = p.W;

    float acc[4][4][4] = {};

    auto issue = [&](int st, int k0) {
        uint32_t aB = sb + (uint32_t)st * 16384u;
        uint32_t bB = sb + 32768u + (uint32_t)st * 16384u;
        #pragma unroll
        for (int i = 0; i < 4; i++) {
            int idx = tid + i*256;
            int r = idx >> 3, c = idx & 7;
            cp16(swz(aB, r, c), X + (size_t)(m0 + r)*NC + k0 + c*8);
        }
        #pragma unroll
        for (int i = 0; i < 4; i++) {
            int idx = tid + i*256;
            int r = idx >> 3, c = idx & 7;
            cp16(swz(bB, r, c), W + (size_t)(n0 + r)*NC + k0 + c*8);
        }
        cp_commit();
    };

    issue(0, 0);
    #pragma unroll 1
    for (int it = 0; it < NIT; ++it) {
        cp_wait0();
        __syncthreads();
        if (it + 1 < NIT) issue((it + 1) & 1, (it + 1)*BK);
        uint32_t aB = sb + (uint32_t)(it & 1) * 16384u;
        uint32_t bB = sb + 32768u + (uint32_t)(it & 1) * 16384u;
        #pragma unroll
        for (int j = 0; j < 4; j++) {
            uint32_t a[4][4], bf[4][2];
            #pragma unroll
            for (int mt = 0; mt < 4; mt++) {
                int row = wm*64 + mt*16 + (lane & 15);
                int c   = 2*j + (lane >> 4);
                ldsm4(a[mt][0], a[mt][1], a[mt][2], a[mt][3], swz(aB, row, c));
            }
            #pragma unroll
            for (int q = 0; q < 2; q++) {
                int row = wn*32 + q*16 + ((lane >> 4) << 3) + (lane & 7);
                int c   = 2*j + ((lane >> 3) & 1);
                uint32_t r0, r1, r2, r3;
                ldsm4(r0, r1, r2, r3, swz(bB, row, c));
                bf[q*2][0] = r0; bf[q*2][1] = r1;
                bf[q*2+1][0] = r2; bf[q*2+1][1] = r3;
            }
            #pragma unroll
            for (int mt = 0; mt < 4; mt++)
                #pragma unroll
                for (int nt = 0; nt < 4; nt++)
                    mma_bf16(acc[mt][nt], a[mt], bf[nt]);
        }
    }

    if (p.mode == 0) {
        __nv_bfloat16* Y = (__nv_bfloat16*)p.Y;
        float scale = p.scale;
        #pragma unroll
        for (int mt = 0; mt < 4; mt++) {
            #pragma unroll
            for (int nt = 0; nt < 4; nt++) {
                int r0 = m0 + wm*64 + mt*16 + g;
                int c0 = n0 + wn*32 + nt*8 + 2*tg;
                float b0 = p.bias[c0], b1 = p.bias[c0 + 1];
                *(__nv_bfloat162*)(Y + (size_t)r0*NC + c0) =
                    __floats2bfloat162_rn((acc[mt][nt][0] + b0)*scale, (acc[mt][nt][1] + b1)*scale);
                *(__nv_bfloat162*)(Y + (size_t)(r0+8)*NC + c0) =
                    __floats2bfloat162_rn((acc[mt][nt][2] + b0)*scale, (acc[mt][nt][3] + b1)*scale);
            }
        }
    } else {
        // V^T store via smem bounce: stage [o 0..127][tok 0..127] half,
        // padded stride 136, then coalesced 16B stores.
        __syncthreads();                         // smem tiles no longer needed
        __half* S = (__half*)smc;                // 128*136*2 = 34816 B
        #pragma unroll
        for (int mt = 0; mt < 4; mt++) {
            #pragma unroll
            for (int nt = 0; nt < 4; nt++) {
                int oL = wn*32 + nt*8 + 2*tg;
                int mL = wm*64 + mt*16 + g;
                float b0 = p.bias[n0 + oL], b1 = p.bias[n0 + oL + 1];
                S[(oL    )*136 + mL    ] = __float2half_rn(acc[mt][nt][0] + b0);
                S[(oL + 1)*136 + mL    ] = __float2half_rn(acc[mt][nt][1] + b1);
                S[(oL    )*136 + mL + 8] = __float2half_rn(acc[mt][nt][2] + b0);
                S[(oL + 1)*136 + mL + 8] = __float2half_rn(acc[mt][nt][3] + b1);
            }
        }
        __syncthreads();
        __half* Y = (__half*)p.Y;
        #pragma unroll
        for (int i = 0; i < 8; i++) {
            int idx = tid + i*256;               // 0..2047
            int o  = idx >> 4;
            int t8 = (idx & 15) * 8;             // 8-token chunk (NT%8==0 -> same batch)
            int gm = m0 + t8;
            int b = gm / NT, n = gm % NT;
            uint4 v = *(uint4*)&S[o*136 + t8];
            *(uint4*)(Y + ((size_t)b*NC + n0 + o)*NT + n) = v;
        }
    }
}

// ---------------- FlashAttention: no-max softmax, deferred l-reduction ------
struct AArgs {
    const __nv_bfloat16 *Q[2], *K[2];
    const __half *Vt[2];
    float *T[2];
    __nv_bfloat16 *Th[2];
    float *Tf[2];
};

static constexpr int ATTN_SMEM_BYTES = 49152;

__global__ __launch_bounds__(256, 2)
void attn_bf(AArgs aa) {
    extern __shared__ char smc[];
    const uint32_t sb  = (uint32_t)__cvta_generic_to_shared(smc);
    const uint32_t sbQ = sb;
    const int z = blockIdx.z;
    const int b = z >> 1, st = z & 1;
    const __nv_bfloat16* Q = aa.Q[st];
    const __nv_bfloat16* K = aa.K[st];
    const __half*       Vt = aa.Vt[st];
    float* T = aa.T[st];
    __nv_bfloat16* Th = aa.Th[st];
    float* Tf = aa.Tf[st];

    const int q0 = blockIdx.x * 128;
    const int h  = blockIdx.y;
    const int tid = threadIdx.x;
    const int lane = tid & 31, warp = tid >> 5;
    const int g = lane >> 2, tg = lane & 3;
    const int wr = warp * 16;
    const size_t base  = ((size_t)b * NT) * NC + h * DH;
    const size_t vbase = ((size_t)b * NC + h * DH) * NT;

    #pragma unroll
    for (int i = 0; i < 4; i++) {
        int idx = tid + i*256;
        int r = idx >> 3, c = idx & 7;
        int row = q0 + r;
        int ok = (row < NT) ? 16 : 0;
        if (row >= NT) row = NT - 1;
        cp16z(swz(sbQ, r, c), Q + base + (size_t)row*NC + c*8, ok);
    }
    auto issueKV = [&](int stg, int kt) {
        uint32_t kB = sb + 16384u + (uint32_t)stg*8192u;
        uint32_t vB = sb + 32768u + (uint32_t)stg*8192u;
        #pragma unroll
        for (int i = 0; i < 2; i++) {
            int idx = tid + i*256;
            int r = idx >> 3, c = idx & 7;
            int krow = kt + r;
            int kok = (krow < NT) ? 16 : 0;
            if (krow >= NT) krow = NT - 1;
            cp16z(swz(kB, r, c), K + base + (size_t)krow*NC + c*8, kok);
            int vtok = kt + c*8;
            int vok = (vtok < NT) ? 16 : 0;
            if (vtok >= NT) vtok = NT - 8;
            cp16z(swz(vB, r, c), Vt + vbase + (size_t)r*NT + vtok, vok);
        }
        cp_commit();
    };
    issueKV(0, 0);

    uint32_t qf[4][4];
    float o[8][4] = {};
    float lrow0 = 0.0f, lrow1 = 0.0f;
    constexpr int NIT = (NT + 63) / 64;            // 25

    #pragma unroll 1
    for (int it = 0; it < NIT; ++it) {
        cp_wait0();
        __syncthreads();
        if (it == 0) {
            #pragma unroll
            for (int j = 0; j < 4; j++) {
                int row = wr + (lane & 15);
                int c   = 2*j + (lane >> 4);
                ldsm4(qf[j][0], qf[j][1], qf[j][2], qf[j][3], swz(sbQ, row, c));
            }
        }
        if (it + 1 < NIT) issueKV((it + 1) & 1, (it + 1)*64);

        const uint32_t kB = sb + 16384u + (uint32_t)((it & 1))*8192u;
        const uint32_t vB = sb + 32768u + (uint32_t)((it & 1))*8192u;
        const int kt = it * 64;

        float s[8][4] = {};
        #pragma unroll
        for (int j = 0; j < 4; j++) {
            #pragma unroll
            for (int q = 0; q < 4; q++) {
                int row = q*16 + ((lane >> 4) << 3) + (lane & 7);
                int c   = 2*j + ((lane >> 3) & 1);
                uint32_t r0, r1, r2, r3;
                ldsm4(r0, r1, r2, r3, swz(kB, row, c));
                uint32_t f0[2] = {r0, r1}, f1[2] = {r2, r3};
                mma_bf16(s[q*2    ], qf[j], f0);
                mma_bf16(s[q*2 + 1], qf[j], f1);
            }
        }

        if (kt + 64 > NT) {
            #pragma unroll
            for (int nt = 0; nt < 8; nt++) {
                int c0 = kt + nt*8 + 2*tg;
                if (c0     >= NT) { s[nt][0] = -1e30f; s[nt][2] = -1e30f; }
                if (c0 + 1 >= NT) { s[nt][1] = -1e30f; s[nt][3] = -1e30f; }
            }
        }

        uint32_t pa[4][4];
        __half2 sh0 = __floats2half2_rn(0.0f, 0.0f);
        __half2 sh1 = __floats2half2_rn(0.0f, 0.0f);
        #pragma unroll
        for (int j = 0; j < 4; j++) {
            uint32_t a0 = ex2h2(s[2*j][0],   s[2*j][1]);
            uint32_t a1 = ex2h2(s[2*j][2],   s[2*j][3]);
            uint32_t a2 = ex2h2(s[2*j+1][0], s[2*j+1][1]);
            uint32_t a3 = ex2h2(s[2*j+1][2], s[2*j+1][3]);
            pa[j][0] = a0; pa[j][1] = a1; pa[j][2] = a2; pa[j][3] = a3;
            sh0 = __hadd2(sh0, __hadd2(*(__half2*)&a0, *(__half2*)&a2));
            sh1 = __hadd2(sh1, __hadd2(*(__half2*)&a1, *(__half2*)&a3));
        }
        float2 f0 = __half22float2(sh0);
        float2 f1 = __half22float2(sh1);
        lrow0 += f0.x + f0.y;
        lrow1 += f1.x + f1.y;

        #pragma unroll
        for (int j = 0; j < 4; j++) {
            #pragma unroll
            for (int q = 0; q < 4; q++) {
                int row = q*16 + ((lane >> 4) << 3) + (lane & 7);
                int c   = 2*j + ((lane >> 3) & 1);
                uint32_t r0, r1, r2, r3;
                ldsm4(r0, r1, r2, r3, swz(vB, row, c));
                uint32_t f0v[2] = {r0, r1}, f1v[2] = {r2, r3};
                mma_f16(o[q*2    ], pa[j], f0v);
                mma_f16(o[q*2 + 1], pa[j], f1v);
            }
        }
    }

    lrow0 += __shfl_xor_sync(0xffffffffu, lrow0, 1);
    lrow0 += __shfl_xor_sync(0xffffffffu, lrow0, 2);
    lrow1 += __shfl_xor_sync(0xffffffffu, lrow1, 1);
    lrow1 += __shfl_xor_sync(0xffffffffu, lrow1, 2);

    int r0 = q0 + wr + g, r1 = r0 + 8;
    float inv0 = 1.0f / lrow0, inv1 = 1.0f / lrow1;
    #pragma unroll
    for (int nt = 0; nt < 8; nt++) {
        int d = nt*8 + 2*tg;
        if (r0 < NT) {
            size_t off = base + (size_t)r0*NC + d;
            float n0 = T[off]     + o[nt][0] * inv0;
            float n1 = T[off + 1] + o[nt][1] * inv0;
            T[off] = n0;  T[off + 1] = n1;
            if (Th) *(__nv_bfloat162*)(Th + off) = __floats2bfloat162_rn(n0, n1);
            if (Tf) { Tf[off] = f2tff(n0); Tf[off + 1] = f2tff(n1); }
        }
        if (r1 < NT) {
            size_t off = base + (size_t)r1*NC + d;
            float n0 = T[off]     + o[nt][2] * inv1;
            float n1 = T[off + 1] + o[nt][3] * inv1;
            T[off] = n0;  T[off + 1] = n1;
            if (Th) *(__nv_bfloat162*)(Th + off) = __floats2bfloat162_rn(n0, n1);
            if (Tf) { Tf[off] = f2tff(n0); Tf[off + 1] = f2tff(n1); }
        }
    }
}

// ---------------- TF32 out-head GEMM (smem-bounced transposed store) --------
struct OArg { const float *X, *W, *bias, *bng, *bnb; float *Y; };
struct OArgs { OArg op[2]; };

__global__ __launch_bounds__(256)
void gemm_out(OArgs oa) {
    constexpr int BM = 128, BN = 64, BK = 32;
    const OArg p = oa.op[blockIdx.z];
    extern __shared__ float smem[];
    const uint32_t sb = (uint32_t)__cvta_generic_to_shared(smem);
    const int tid = threadIdx.x, lane = tid & 31, warp = tid >> 5;
    const int g = lane >> 2, tg = lane & 3;
    const int wm = warp >> 1, wn = warp & 1;
    const int m0 = blockIdx.y * BM, n0 = blockIdx.x * BN;
    const float* X = p.X;
    const float* W = p.W;

    float acc[2][4][4] = {};

    auto issue = [&](int st, int k0) {
        uint32_t aB = sb + (uint32_t)(st*BM*BK)*4u;
        uint32_t bB = sb + (uint32_t)(2*BM*BK + st*BN*BK)*4u;
        #pragma unroll
        for (int i = 0; i < 4; i++) {
            int idx = tid + i*256;
            int r = idx >> 3, c4 = idx & 7;
            cp16(aB + 4u*(r*32 + ((c4 ^ (r & 7)) << 2)),
                 X + (size_t)(m0 + r)*NC + k0 + c4*4);
        }
        #pragma unroll
        for (int i = 0; i < 2; i++) {
            int idx = tid + i*256;
            int r = idx >> 3, c4 = idx & 7;
            cp16(bB + 4u*(r*32 + ((c4 ^ (r & 7)) << 2)),
                 W + (size_t)(n0 + r)*NC + k0 + c4*4);
        }
        cp_commit();
    };

    issue(0, 0);
    #pragma unroll 1
    for (int it = 0; it < NC/BK; ++it) {
        cp_wait0();
        __syncthreads();
        if (it + 1 < NC/BK) issue((it + 1) & 1, (it + 1)*BK);
        const uint32_t aBase = sb + (uint32_t)((it & 1)*BM*BK)*4u;
        const uint32_t bBase = sb + (uint32_t)(2*BM*BK + (it & 1)*BN*BK)*4u;
        #pragma unroll
        for (int kk = 0; kk < BK; kk += 8) {
            const int c0 = kk >> 2;
            uint32_t a[2][4], b[4][2];
            #pragma unroll
            for (int mt = 0; mt < 2; mt++) {
                int row = wm*32 + mt*16 + (lane & 15);
                int c4  = c0 + (lane >> 4);
                ldsm4(a[mt][0], a[mt][1], a[mt][2], a[mt][3],
                      aBase + 4u*(row*32 + ((c4 ^ (row & 7)) << 2)));
            }
            #pragma unroll
            for (int pq = 0; pq < 2; pq++) {
                int row = wn*32 + ((pq*2 + ((lane >> 4) & 1)) << 3) + (lane & 7);
                int c4  = c0 + ((lane >> 3) & 1);
                ldsm4(b[pq*2][0], b[pq*2][1], b[pq*2+1][0], b[pq*2+1][1],
                      bBase + 4u*(row*32 + ((c4 ^ (row & 7)) << 2)));
            }
            #pragma unroll
            for (int mt = 0; mt < 2; mt++)
                #pragma unroll
                for (int nt = 0; nt < 4; nt++)
                    mma_tf32(acc[mt][nt], a[mt], b[nt]);
        }
    }

    // epilogue: relu/bn into padded smem [oc 0..63][tok 0..127], then
    // coalesced float4 stores.
    const float bns = rsqrtf(1.0f + 1e-5f);
    __syncthreads();
    float* S = smem;                             // 64*132*4 = 33792 B
    #pragma unroll
    for (int mt = 0; mt < 2; mt++) {
        #pragma unroll
        for (int nt = 0; nt < 4; nt++) {
            int oL = wn*32 + nt*8 + 2*tg;
            int mL = wm*32 + mt*16 + g;
            #pragma unroll
            for (int e = 0; e < 4; e++) {
                int oc = n0 + oL + (e & 1);
                float z = acc[mt][nt][e] + p.bias[oc];
                z = fmaxf(z, 0.0f) * bns;
                S[(oL + (e & 1))*132 + mL + (e >> 1)*8] = z * p.bng[oc] + p.bnb[oc];
            }
        }
    }
    __syncthreads();
    #pragma unroll
    for (int i = 0; i < 8; i++) {
        int idx = tid + i*256;                   // 0..2047
        int oc = idx >> 5;
        int t4 = (idx & 31) * 4;                 // 4-token chunk (NT%4==0)
        int gm = m0 + t4;
        int b = gm / NT, n = gm % NT;
        float4 v = *(float4*)&S[oc*132 + t4];
        *(float4*)(p.Y + ((size_t)b*NC + n0 + oc)*NT + n) = v;
    }
}

// ---------------------------------------------------------------------------
extern "C" void kernel_launch(void* const* d_in, const int* in_sizes, int n_in,
                              void* d_out, int out_size) {
    const float* x1   = (const float*)d_in[0];
    const float* x2   = (const float*)d_in[1];
    const float* Wq1  = (const float*)d_in[2];
    const float* bq1  = (const float*)d_in[3];
    const float* Wk1  = (const float*)d_in[4];
    const float* bk1  = (const float*)d_in[5];
    const float* Wv1  = (const float*)d_in[6];
    const float* bv1  = (const float*)d_in[7];
    const float* ln1g = (const float*)d_in[8];
    const float* ln1b = (const float*)d_in[9];
    const float* Wq2  = (const float*)d_in[10];
    const float* bq2  = (const float*)d_in[11];
    const float* Wk2  = (const float*)d_in[12];
    const float* bk2  = (const float*)d_in[13];
    const float* Wv2  = (const float*)d_in[14];
    const float* bv2  = (const float*)d_in[15];
    const float* ln2g = (const float*)d_in[16];
    const float* ln2b = (const float*)d_in[17];
    const float* o1w  = (const float*)d_in[18];
    const float* o1b  = (const float*)d_in[19];
    const float* bn1g = (const float*)d_in[20];
    const float* bn1b = (const float*)d_in[21];
    const float* o2w  = (const float*)d_in[22];
    const float* o2b  = (const float*)d_in[23];
    const float* bn2g = (const float*)d_in[24];
    const float* bn2b = (const float*)d_in[25];
    float* out = (float*)d_out;

    float *t1, *t2, *t1f, *t2f, *wf;
    void *th1, *th2, *ln1h, *ln2h, *q1h, *k1h, *v1h, *q2h, *k2h, *v2h, *wh;
    cudaGetSymbolAddress((void**)&t1,  g_t1);
    cudaGetSymbolAddress((void**)&t2,  g_t2);
    cudaGetSymbolAddress((void**)&t1f, g_t1f);
    cudaGetSymbolAddress((void**)&t2f, g_t2f);
    cudaGetSymbolAddress(&th1,  g_th1);
    cudaGetSymbolAddress(&th2,  g_th2);
    cudaGetSymbolAddress(&ln1h, g_ln1h);
    cudaGetSymbolAddress(&ln2h, g_ln2h);
    cudaGetSymbolAddress(&q1h, g_q1h);
    cudaGetSymbolAddress(&k1h, g_k1h);
    cudaGetSymbolAddress(&v1h, g_v1h);
    cudaGetSymbolAddress(&q2h, g_q2h);
    cudaGetSymbolAddress(&k2h, g_k2h);
    cudaGetSymbolAddress(&v2h, g_v2h);
    cudaGetSymbolAddress(&wh,  g_wh);
    cudaGetSymbolAddress((void**)&wf, g_wf);
    __nv_bfloat16 *TH1 = (__nv_bfloat16*)th1, *TH2 = (__nv_bfloat16*)th2;
    __nv_bfloat16 *LN1 = (__nv_bfloat16*)ln1h, *LN2 = (__nv_bfloat16*)ln2h;
    __nv_bfloat16 *WH = (__nv_bfloat16*)wh;
    __nv_bfloat16 *Q1 = (__nv_bfloat16*)q1h, *K1 = (__nv_bfloat16*)k1h;
    __nv_bfloat16 *Q2 = (__nv_bfloat16*)q2h, *K2 = (__nv_bfloat16*)k2h;
    __half *V1 = (__half*)v1h, *V2 = (__half*)v2h;

    const int OUT_SMEM = 49152;
    cudaFuncSetAttribute(gemm_proj, cudaFuncAttributeMaxDynamicSharedMemorySize, PROJ_SMEM_BYTES);
    cudaFuncSetAttribute(gemm_out,  cudaFuncAttributeMaxDynamicSharedMemorySize, OUT_SMEM);
    cudaFuncSetAttribute(attn_bf,   cudaFuncAttributeMaxDynamicSharedMemorySize, ATTN_SMEM_BYTES);

    WPtrs wp;
    wp.p[0] = Wq1; wp.p[1] = Wk1; wp.p[2] = Wv1;
    wp.p[3] = Wq2; wp.p[4] = Wk2; wp.p[5] = Wv2;
    wp.p[6] = o1w; wp.p[7] = o2w;
    wcvt_kernel<<<dim3(N2/1024, 20), 256>>>(wp, WH, wf);

    dim3 tokGrid(NT/32, NC/32, 2*NB), tokBlk(32, 8);
    tok_kernel<<<tokGrid, tokBlk>>>(x1, t1, TH1, x2, t2, TH2);

    dim3 pGrid(NC/128, NM/128, 6);          // (4, 49, 6)
    dim3 aGrid((NT + 127)/128, NH, 2*NB);   // (13, 8, 8)
    dim3 oGrid(NC/64, NM/128, 2);           // (8, 49, 2)
    const float qs = 0.125f * LOG2E, one = 1.0f;

    for (int i = 0; i < 3; i++) {
        ln_kernel<<<dim3(NM/8, 2), 256>>>(t1, ln1g + i*NC, ln1b + i*NC, LN1,
                                          t2, ln2g + i*NC, ln2b + i*NC, LN2);
        PArgs pa;
        pa.op[0] = { LN1, WH + (size_t)(0*3 + i)*N2, bq1 + i*NC, Q1, qs,  0 };
        pa.op[1] = { TH2, WH + (size_t)(1*3 + i)*N2, bk1 + i*NC, K1, one, 0 };
        pa.op[2] = { TH2, WH + (size_t)(2*3 + i)*N2, bv1 + i*NC, V1, one, 1 };
        pa.op[3] = { LN2, WH + (size_t)(3*3 + i)*N2, bq2 + i*NC, Q2, qs,  0 };
        pa.op[4] = { TH1, WH + (size_t)(4*3 + i)*N2, bk2 + i*NC, K2, one, 0 };
        pa.op[5] = { TH1, WH + (size_t)(5*3 + i)*N2, bv2 + i*NC, V2, one, 1 };
        gemm_proj<<<pGrid, 256, PROJ_SMEM_BYTES>>>(pa);

        bool last = (i == 2);
        AArgs aa;
        aa.Q[0] = Q1;  aa.Q[1] = Q2;
        aa.K[0] = K1;  aa.K[1] = K2;
        aa.Vt[0] = V1; aa.Vt[1] = V2;
        aa.T[0] = t1;  aa.T[1] = t2;
        aa.Th[0] = last ? nullptr : TH1;  aa.Th[1] = last ? nullptr : TH2;
        aa.Tf[0] = last ? t1f : nullptr;  aa.Tf[1] = last ? t2f : nullptr;
        attn_bf<<<aGrid, 256, ATTN_SMEM_BYTES>>>(aa);
    }

    OArgs oa;
    oa.op[0] = { t1f, wf,      o1b, bn1g, bn1b, out };
    oa.op[1] = { t2f, wf + N2, o2b, bn2g, bn2b, out + (size_t)NB*NC*NT };
    gemm_out<<<oGrid, 256, OUT_SMEM>>>(oa);
}

// round 17
// speedup vs baseline: 1.1017x; 1.0628x over previous
#include <cuda_runtime.h>
#include <cuda_bf16.h>
#include <cuda_fp16.h>
#include <cstdint>

static constexpr int NB = 4, NT = 1568, NC = 512, NH = 8, DH = 64;
static constexpr int NM = NB * NT;   // 6272
static constexpr int N2 = NC * NC;   // 262144
static constexpr float LOG2E = 1.4426950408889634f;

// ---------------- scratch ---------------------------------------------------
__device__ float g_t1 [NB*NT*NC];
__device__ float g_t2 [NB*NT*NC];
__device__ float g_t1f[NB*NT*NC];
__device__ float g_t2f[NB*NT*NC];
__device__ float g_th1[NB*NT*NC/2];
__device__ float g_th2[NB*NT*NC/2];
__device__ float g_ln1h[NB*NT*NC/2];
__device__ float g_ln2h[NB*NT*NC/2];
__device__ float g_q1h[NB*NT*NC/2];
__device__ float g_k1h[NB*NT*NC/2];
__device__ float g_v1h[NB*NT*NC/2];   // V^T f16: [b][c][tok]
__device__ float g_q2h[NB*NT*NC/2];
__device__ float g_k2h[NB*NT*NC/2];
__device__ float g_v2h[NB*NT*NC/2];
__device__ float g_wh [18*N2/2];
__device__ float g_wf [2*N2];

// ---------------- helpers ---------------------------------------------------
__device__ __forceinline__ uint32_t f2tf(float f) {
    uint32_t u;
    asm("cvt.rna.tf32.f32 %0, %1;\n" : "=r"(u) : "f"(f));
    return u;
}
__device__ __forceinline__ float f2tff(float f) { return __uint_as_float(f2tf(f)); }

__device__ __forceinline__ void mma_bf16(float* c, const uint32_t* a, const uint32_t* b) {
    asm volatile(
        "mma.sync.aligned.m16n8k16.row.col.f32.bf16.bf16.f32 "
        "{%0,%1,%2,%3}, {%4,%5,%6,%7}, {%8,%9}, {%0,%1,%2,%3};\n"
        : "+f"(c[0]), "+f"(c[1]), "+f"(c[2]), "+f"(c[3])
        : "r"(a[0]), "r"(a[1]), "r"(a[2]), "r"(a[3]), "r"(b[0]), "r"(b[1]));
}
__device__ __forceinline__ void mma_f16(float* c, const uint32_t* a, const uint32_t* b) {
    asm volatile(
        "mma.sync.aligned.m16n8k16.row.col.f32.f16.f16.f32 "
        "{%0,%1,%2,%3}, {%4,%5,%6,%7}, {%8,%9}, {%0,%1,%2,%3};\n"
        : "+f"(c[0]), "+f"(c[1]), "+f"(c[2]), "+f"(c[3])
        : "r"(a[0]), "r"(a[1]), "r"(a[2]), "r"(a[3]), "r"(b[0]), "r"(b[1]));
}
__device__ __forceinline__ void mma_tf32(float* c, const uint32_t* a, const uint32_t* b) {
    asm volatile(
        "mma.sync.aligned.m16n8k8.row.col.f32.tf32.tf32.f32 "
        "{%0,%1,%2,%3}, {%4,%5,%6,%7}, {%8,%9}, {%0,%1,%2,%3};\n"
        : "+f"(c[0]), "+f"(c[1]), "+f"(c[2]), "+f"(c[3])
        : "r"(a[0]), "r"(a[1]), "r"(a[2]), "r"(a[3]), "r"(b[0]), "r"(b[1]));
}
__device__ __forceinline__ void ldsm4(uint32_t& r0, uint32_t& r1, uint32_t& r2, uint32_t& r3,
                                      uint32_t addr) {
    asm volatile("ldmatrix.sync.aligned.m8n8.x4.shared.b16 {%0,%1,%2,%3}, [%4];\n"
                 : "=r"(r0), "=r"(r1), "=r"(r2), "=r"(r3) : "r"(addr));
}
__device__ __forceinline__ uint32_t ex2h2(float lo, float hi) {
    uint32_t h, d;
    asm("cvt.rn.f16x2.f32 %0, %1, %2;\n" : "=r"(h) : "f"(hi), "f"(lo));
    asm("ex2.approx.f16x2 %0, %1;\n" : "=r"(d) : "r"(h));
    return d;
}
__device__ __forceinline__ void cp16(uint32_t dst, const void* src) {
    asm volatile("cp.async.cg.shared.global [%0], [%1], 16;\n" :: "r"(dst), "l"(src));
}
__device__ __forceinline__ void cp16z(uint32_t dst, const void* src, int bytes) {
    asm volatile("cp.async.cg.shared.global [%0], [%1], 16, %2;\n" :: "r"(dst), "l"(src), "r"(bytes));
}
__device__ __forceinline__ void cp_commit() { asm volatile("cp.async.commit_group;\n"); }
__device__ __forceinline__ void cp_wait0()  { asm volatile("cp.async.wait_group 0;\n"); }

__device__ __forceinline__ uint32_t swz(uint32_t base, int row, int c) {
    return base + (uint32_t)((row * 8 + (c ^ (row & 7))) << 4);
}

// ---------------- weight pre-conversion ------------------------------------
struct WPtrs { const float* p[8]; };
__global__ void wcvt_kernel(WPtrs w, __nv_bfloat16* __restrict__ dh, float* __restrict__ df) {
    int mat = blockIdx.y;
    const float* src;
    if (mat < 18) src = w.p[mat/3] + (size_t)(mat%3) * N2;
    else          src = w.p[6 + (mat - 18)];
    int i = (blockIdx.x * 256 + threadIdx.x) * 4;
    float4 v = *(const float4*)(src + i);
    if (mat < 18) {
        __nv_bfloat162* d = (__nv_bfloat162*)(dh + (size_t)mat * N2 + i);
        d[0] = __floats2bfloat162_rn(v.x, v.y);
        d[1] = __floats2bfloat162_rn(v.z, v.w);
    } else {
        float4 o;
        o.x = f2tff(v.x); o.y = f2tff(v.y); o.z = f2tff(v.z); o.w = f2tff(v.w);
        *(float4*)(df + (size_t)(mat - 18) * N2 + i) = o;
    }
}

// ---------------- tokenize --------------------------------------------------
__global__ void tok_kernel(const float* __restrict__ x1, float* __restrict__ t1o,
                           __nv_bfloat16* __restrict__ th1o,
                           const float* __restrict__ x2, float* __restrict__ t2o,
                           __nv_bfloat16* __restrict__ th2o) {
    __shared__ float tile[32][33];
    int z = blockIdx.z;
    int b = z >> 1, st = z & 1;
    const float* x = st ? x2 : x1;
    float* t = st ? t2o : t1o;
    __nv_bfloat16* th = st ? th2o : th1o;
    int n0 = blockIdx.x * 32, c0 = blockIdx.y * 32;
    int nx = n0 + threadIdx.x;
    #pragma unroll
    for (int i = 0; i < 32; i += 8) {
        int c = c0 + threadIdx.y + i;
        tile[threadIdx.y + i][threadIdx.x] = x[((size_t)b*NC + c)*NT + nx];
    }
    __syncthreads();
    int cx = c0 + threadIdx.x;
    #pragma unroll
    for (int i = 0; i < 32; i += 8) {
        int n = n0 + threadIdx.y + i;
        float v = tile[threadIdx.x][threadIdx.y + i];
        size_t off = ((size_t)b*NT + n)*NC + cx;
        t[off]  = v;
        th[off] = __float2bfloat16_rn(v);
    }
}

// ---------------- LayerNorm: warp-per-row -----------------------------------
__global__ __launch_bounds__(256)
void ln_kernel(const float* __restrict__ tA, const float* __restrict__ gA,
               const float* __restrict__ bA, __nv_bfloat16* __restrict__ oA,
               const float* __restrict__ tB, const float* __restrict__ gB,
               const float* __restrict__ bB, __nv_bfloat16* __restrict__ oB) {
    const float* t = blockIdx.y ? tB : tA;
    const float* gamma = blockIdx.y ? gB : gA;
    const float* beta  = blockIdx.y ? bB : bA;
    __nv_bfloat16* out = blockIdx.y ? oB : oA;

    int row  = blockIdx.x * 8 + (threadIdx.x >> 5);
    int lane = threadIdx.x & 31;

    const float4* x4 = (const float4*)(t + (size_t)row * NC);
    float4 v[4];
    float s = 0.0f, s2 = 0.0f;
    #pragma unroll
    for (int j = 0; j < 4; j++) {
        v[j] = x4[j*32 + lane];
        s  += v[j].x + v[j].y + v[j].z + v[j].w;
        s2 += v[j].x*v[j].x + v[j].y*v[j].y + v[j].z*v[j].z + v[j].w*v[j].w;
    }
    #pragma unroll
    for (int o = 16; o > 0; o >>= 1) {
        s  += __shfl_xor_sync(0xffffffffu, s,  o);
        s2 += __shfl_xor_sync(0xffffffffu, s2, o);
    }
    float mean = s * (1.0f / NC);
    float var  = s2 * (1.0f / NC) - mean * mean;
    float rstd = rsqrtf(var + 1e-5f);

    uint2* o8 = (uint2*)(out + (size_t)row * NC);
    #pragma unroll
    for (int j = 0; j < 4; j++) {
        float4 g4 = ((const float4*)gamma)[j*32 + lane];
        float4 b4 = ((const float4*)beta )[j*32 + lane];
        __nv_bfloat162 lo = __floats2bfloat162_rn((v[j].x - mean)*rstd*g4.x + b4.x,
                                                  (v[j].y - mean)*rstd*g4.y + b4.y);
        __nv_bfloat162 hi = __floats2bfloat162_rn((v[j].z - mean)*rstd*g4.z + b4.z,
                                                  (v[j].w - mean)*rstd*g4.w + b4.w);
        uint2 u;
        u.x = *(uint32_t*)&lo;
        u.y = *(uint32_t*)&hi;
        o8[j*32 + lane] = u;
    }
}

// ---------------- merged bf16 proj GEMM (2-stage pipeline) ------------------
struct PArg {
    const __nv_bfloat16 *A, *W;
    const float *bias;
    void *Y;
    float scale;
    int mode;
};
struct PArgs { PArg op[6]; };

static constexpr int PROJ_SMEM_BYTES = 65536;

__global__ __launch_bounds__(256, 2)
void gemm_proj(PArgs pa) {
    constexpr int BM = 128, BN = 128, BK = 64, NIT = NC / BK;   // 8
    const PArg p = pa.op[blockIdx.z];
    extern __shared__ char smc[];
    const uint32_t sb = (uint32_t)__cvta_generic_to_shared(smc);
    const int tid = threadIdx.x, lane = tid & 31, warp = tid >> 5;
    const int g = lane >> 2, tg = lane & 3;
    const int wm = warp >> 2, wn = warp & 3;
    const int m0 = blockIdx.y * BM, n0 = blockIdx.x * BN;
    const __nv_bfloat16* X = p.A;
    const __nv_bfloat16* W = p.W;

    float acc[4][4][4] = {};

    auto issue = [&](int st, int k0) {
        uint32_t aB = sb + (uint32_t)st * 16384u;
        uint32_t bB = sb + 32768u + (uint32_t)st * 16384u;
        #pragma unroll
        for (int i = 0; i < 4; i++) {
            int idx = tid + i*256;
            int r = idx >> 3, c = idx & 7;
            cp16(swz(aB, r, c), X + (size_t)(m0 + r)*NC + k0 + c*8);
        }
        #pragma unroll
        for (int i = 0; i < 4; i++) {
            int idx = tid + i*256;
            int r = idx >> 3, c = idx & 7;
            cp16(swz(bB, r, c), W + (size_t)(n0 + r)*NC + k0 + c*8);
        }
        cp_commit();
    };

    issue(0, 0);
    #pragma unroll 1
    for (int it = 0; it < NIT; ++it) {
        cp_wait0();
        __syncthreads();
        if (it + 1 < NIT) issue((it + 1) & 1, (it + 1)*BK);
        uint32_t aB = sb + (uint32_t)(it & 1) * 16384u;
        uint32_t bB = sb + 32768u + (uint32_t)(it & 1) * 16384u;
        #pragma unroll
        for (int j = 0; j < 4; j++) {
            uint32_t a[4][4], bf[4][2];
            #pragma unroll
            for (int mt = 0; mt < 4; mt++) {
                int row = wm*64 + mt*16 + (lane & 15);
                int c   = 2*j + (lane >> 4);
                ldsm4(a[mt][0], a[mt][1], a[mt][2], a[mt][3], swz(aB, row, c));
            }
            #pragma unroll
            for (int q = 0; q < 2; q++) {
                int row = wn*32 + q*16 + ((lane >> 4) << 3) + (lane & 7);
                int c   = 2*j + ((lane >> 3) & 1);
                uint32_t r0, r1, r2, r3;
                ldsm4(r0, r1, r2, r3, swz(bB, row, c));
                bf[q*2][0] = r0; bf[q*2][1] = r1;
                bf[q*2+1][0] = r2; bf[q*2+1][1] = r3;
            }
            #pragma unroll
            for (int mt = 0; mt < 4; mt++)
                #pragma unroll
                for (int nt = 0; nt < 4; nt++)
                    mma_bf16(acc[mt][nt], a[mt], bf[nt]);
        }
    }

    if (p.mode == 0) {
        __nv_bfloat16* Y = (__nv_bfloat16*)p.Y;
        float scale = p.scale;
        #pragma unroll
        for (int mt = 0; mt < 4; mt++) {
            #pragma unroll
            for (int nt = 0; nt < 4; nt++) {
                int r0 = m0 + wm*64 + mt*16 + g;
                int c0 = n0 + wn*32 + nt*8 + 2*tg;
                float b0 = p.bias[c0], b1 = p.bias[c0 + 1];
                *(__nv_bfloat162*)(Y + (size_t)r0*NC + c0) =
                    __floats2bfloat162_rn((acc[mt][nt][0] + b0)*scale, (acc[mt][nt][1] + b1)*scale);
                *(__nv_bfloat162*)(Y + (size_t)(r0+8)*NC + c0) =
                    __floats2bfloat162_rn((acc[mt][nt][2] + b0)*scale, (acc[mt][nt][3] + b1)*scale);
            }
        }
    } else {
        // V^T store via smem bounce (coalesced 16B stores)
        __syncthreads();
        __half* S = (__half*)smc;                // 128*136*2 = 34816 B
        #pragma unroll
        for (int mt = 0; mt < 4; mt++) {
            #pragma unroll
            for (int nt = 0; nt < 4; nt++) {
                int oL = wn*32 + nt*8 + 2*tg;
                int mL = wm*64 + mt*16 + g;
                float b0 = p.bias[n0 + oL], b1 = p.bias[n0 + oL + 1];
                S[(oL    )*136 + mL    ] = __float2half_rn(acc[mt][nt][0] + b0);
                S[(oL + 1)*136 + mL    ] = __float2half_rn(acc[mt][nt][1] + b1);
                S[(oL    )*136 + mL + 8] = __float2half_rn(acc[mt][nt][2] + b0);
                S[(oL + 1)*136 + mL + 8] = __float2half_rn(acc[mt][nt][3] + b1);
            }
        }
        __syncthreads();
        __half* Y = (__half*)p.Y;
        #pragma unroll
        for (int i = 0; i < 8; i++) {
            int idx = tid + i*256;               // 0..2047
            int o  = idx >> 4;
            int t8 = (idx & 15) * 8;             // 8-token chunk (NT%8==0)
            int gm = m0 + t8;
            int b = gm / NT, n = gm % NT;
            uint4 v = *(uint4*)&S[o*136 + t8];
            *(uint4*)(Y + ((size_t)b*NC + n0 + o)*NT + n) = v;
        }
    }
}

// ---------------- FlashAttention: no-max softmax, coalesced epilogue --------
struct AArgs {
    const __nv_bfloat16 *Q[2], *K[2];
    const __half *Vt[2];
    float *T[2];
    __nv_bfloat16 *Th[2];
    float *Tf[2];
};

static constexpr int ATTN_SMEM_BYTES = 49152;

__global__ __launch_bounds__(256, 2)
void attn_bf(AArgs aa) {
    extern __shared__ char smc[];
    const uint32_t sb  = (uint32_t)__cvta_generic_to_shared(smc);
    const uint32_t sbQ = sb;
    const int z = blockIdx.z;
    const int b = z >> 1, st = z & 1;
    const __nv_bfloat16* Q = aa.Q[st];
    const __nv_bfloat16* K = aa.K[st];
    const __half*       Vt = aa.Vt[st];
    float* T = aa.T[st];
    __nv_bfloat16* Th = aa.Th[st];
    float* Tf = aa.Tf[st];

    const int q0 = blockIdx.x * 128;
    const int h  = blockIdx.y;
    const int tid = threadIdx.x;
    const int lane = tid & 31, warp = tid >> 5;
    const int g = lane >> 2, tg = lane & 3;
    const int wr = warp * 16;
    const size_t base  = ((size_t)b * NT) * NC + h * DH;
    const size_t vbase = ((size_t)b * NC + h * DH) * NT;

    #pragma unroll
    for (int i = 0; i < 4; i++) {
        int idx = tid + i*256;
        int r = idx >> 3, c = idx & 7;
        int row = q0 + r;
        int ok = (row < NT) ? 16 : 0;
        if (row >= NT) row = NT - 1;
        cp16z(swz(sbQ, r, c), Q + base + (size_t)row*NC + c*8, ok);
    }
    auto issueKV = [&](int stg, int kt) {
        uint32_t kB = sb + 16384u + (uint32_t)stg*8192u;
        uint32_t vB = sb + 32768u + (uint32_t)stg*8192u;
        #pragma unroll
        for (int i = 0; i < 2; i++) {
            int idx = tid + i*256;
            int r = idx >> 3, c = idx & 7;
            int krow = kt + r;
            int kok = (krow < NT) ? 16 : 0;
            if (krow >= NT) krow = NT - 1;
            cp16z(swz(kB, r, c), K + base + (size_t)krow*NC + c*8, kok);
            int vtok = kt + c*8;
            int vok = (vtok < NT) ? 16 : 0;
            if (vtok >= NT) vtok = NT - 8;
            cp16z(swz(vB, r, c), Vt + vbase + (size_t)r*NT + vtok, vok);
        }
        cp_commit();
    };
    issueKV(0, 0);

    uint32_t qf[4][4];
    float o[8][4] = {};
    float lrow0 = 0.0f, lrow1 = 0.0f;
    constexpr int NIT = (NT + 63) / 64;            // 25

    #pragma unroll 1
    for (int it = 0; it < NIT; ++it) {
        cp_wait0();
        __syncthreads();
        if (it == 0) {
            #pragma unroll
            for (int j = 0; j < 4; j++) {
                int row = wr + (lane & 15);
                int c   = 2*j + (lane >> 4);
                ldsm4(qf[j][0], qf[j][1], qf[j][2], qf[j][3], swz(sbQ, row, c));
            }
        }
        if (it + 1 < NIT) issueKV((it + 1) & 1, (it + 1)*64);

        const uint32_t kB = sb + 16384u + (uint32_t)((it & 1))*8192u;
        const uint32_t vB = sb + 32768u + (uint32_t)((it & 1))*8192u;
        const int kt = it * 64;

        float s[8][4] = {};
        #pragma unroll
        for (int j = 0; j < 4; j++) {
            #pragma unroll
            for (int q = 0; q < 4; q++) {
                int row = q*16 + ((lane >> 4) << 3) + (lane & 7);
                int c   = 2*j + ((lane >> 3) & 1);
                uint32_t r0, r1, r2, r3;
                ldsm4(r0, r1, r2, r3, swz(kB, row, c));
                uint32_t f0[2] = {r0, r1}, f1[2] = {r2, r3};
                mma_bf16(s[q*2    ], qf[j], f0);
                mma_bf16(s[q*2 + 1], qf[j], f1);
            }
        }

        if (kt + 64 > NT) {
            #pragma unroll
            for (int nt = 0; nt < 8; nt++) {
                int c0 = kt + nt*8 + 2*tg;
                if (c0     >= NT) { s[nt][0] = -1e30f; s[nt][2] = -1e30f; }
                if (c0 + 1 >= NT) { s[nt][1] = -1e30f; s[nt][3] = -1e30f; }
            }
        }

        uint32_t pa[4][4];
        __half2 sh0 = __floats2half2_rn(0.0f, 0.0f);
        __half2 sh1 = __floats2half2_rn(0.0f, 0.0f);
        #pragma unroll
        for (int j = 0; j < 4; j++) {
            uint32_t a0 = ex2h2(s[2*j][0],   s[2*j][1]);
            uint32_t a1 = ex2h2(s[2*j][2],   s[2*j][3]);
            uint32_t a2 = ex2h2(s[2*j+1][0], s[2*j+1][1]);
            uint32_t a3 = ex2h2(s[2*j+1][2], s[2*j+1][3]);
            pa[j][0] = a0; pa[j][1] = a1; pa[j][2] = a2; pa[j][3] = a3;
            sh0 = __hadd2(sh0, __hadd2(*(__half2*)&a0, *(__half2*)&a2));
            sh1 = __hadd2(sh1, __hadd2(*(__half2*)&a1, *(__half2*)&a3));
        }
        float2 f0 = __half22float2(sh0);
        float2 f1 = __half22float2(sh1);
        lrow0 += f0.x + f0.y;
        lrow1 += f1.x + f1.y;

        #pragma unroll
        for (int j = 0; j < 4; j++) {
            #pragma unroll
            for (int q = 0; q < 4; q++) {
                int row = q*16 + ((lane >> 4) << 3) + (lane & 7);
                int c   = 2*j + ((lane >> 3) & 1);
                uint32_t r0, r1, r2, r3;
                ldsm4(r0, r1, r2, r3, swz(vB, row, c));
                uint32_t f0v[2] = {r0, r1}, f1v[2] = {r2, r3};
                mma_f16(o[q*2    ], pa[j], f0v);
                mma_f16(o[q*2 + 1], pa[j], f1v);
            }
        }
    }

    // deferred cross-lane l reduction
    lrow0 += __shfl_xor_sync(0xffffffffu, lrow0, 1);
    lrow0 += __shfl_xor_sync(0xffffffffu, lrow0, 2);
    lrow1 += __shfl_xor_sync(0xffffffffu, lrow1, 1);
    lrow1 += __shfl_xor_sync(0xffffffffu, lrow1, 2);
    float inv0 = 1.0f / lrow0, inv1 = 1.0f / lrow1;

    // epilogue: stage normalized O in smem, then coalesced RMW of T + mirrors
    __syncthreads();                               // mainloop smem now dead
    float* S = (float*)smc;                        // [128][68] = 34816 B
    #pragma unroll
    for (int nt = 0; nt < 8; nt++) {
        int d = nt*8 + 2*tg;
        float2 w0 = make_float2(o[nt][0]*inv0, o[nt][1]*inv0);
        float2 w1 = make_float2(o[nt][2]*inv1, o[nt][3]*inv1);
        *(float2*)&S[(wr + g    )*68 + d] = w0;
        *(float2*)&S[(wr + g + 8)*68 + d] = w1;
    }
    __syncthreads();
    #pragma unroll
    for (int i = 0; i < 8; i++) {
        int idx = tid + i*256;                     // 0..2047
        int r = idx >> 4, c4 = (idx & 15) * 4;
        int row = q0 + r;
        if (row < NT) {
            size_t off = base + (size_t)row*NC + c4;
            float4 t = *(float4*)(T + off);
            float4 s4 = *(float4*)&S[r*68 + c4];
            t.x += s4.x; t.y += s4.y; t.z += s4.z; t.w += s4.w;
            *(float4*)(T + off) = t;
            if (Th) {
                __nv_bfloat162 lo = __floats2bfloat162_rn(t.x, t.y);
                __nv_bfloat162 hi = __floats2bfloat162_rn(t.z, t.w);
                uint2 u;
                u.x = *(uint32_t*)&lo;
                u.y = *(uint32_t*)&hi;
                *(uint2*)(Th + off) = u;
            }
            if (Tf) {
                float4 f;
                f.x = f2tff(t.x); f.y = f2tff(t.y);
                f.z = f2tff(t.z); f.w = f2tff(t.w);
                *(float4*)(Tf + off) = f;
            }
        }
    }
}

// ---------------- TF32 out-head GEMM (smem-bounced transposed store) --------
struct OArg { const float *X, *W, *bias, *bng, *bnb; float *Y; };
struct OArgs { OArg op[2]; };

__global__ __launch_bounds__(256)
void gemm_out(OArgs oa) {
    constexpr int BM = 128, BN = 64, BK = 32;
    const OArg p = oa.op[blockIdx.z];
    extern __shared__ float smem[];
    const uint32_t sb = (uint32_t)__cvta_generic_to_shared(smem);
    const int tid = threadIdx.x, lane = tid & 31, warp = tid >> 5;
    const int g = lane >> 2, tg = lane & 3;
    const int wm = warp >> 1, wn = warp & 1;
    const int m0 = blockIdx.y * BM, n0 = blockIdx.x * BN;
    const float* X = p.X;
    const float* W = p.W;

    float acc[2][4][4] = {};

    auto issue = [&](int st, int k0) {
        uint32_t aB = sb + (uint32_t)(st*BM*BK)*4u;
        uint32_t bB = sb + (uint32_t)(2*BM*BK + st*BN*BK)*4u;
        #pragma unroll
        for (int i = 0; i < 4; i++) {
            int idx = tid + i*256;
            int r = idx >> 3, c4 = idx & 7;
            cp16(aB + 4u*(r*32 + ((c4 ^ (r & 7)) << 2)),
                 X + (size_t)(m0 + r)*NC + k0 + c4*4);
        }
        #pragma unroll
        for (int i = 0; i < 2; i++) {
            int idx = tid + i*256;
            int r = idx >> 3, c4 = idx & 7;
            cp16(bB + 4u*(r*32 + ((c4 ^ (r & 7)) << 2)),
                 W + (size_t)(n0 + r)*NC + k0 + c4*4);
        }
        cp_commit();
    };

    issue(0, 0);
    #pragma unroll 1
    for (int it = 0; it < NC/BK; ++it) {
        cp_wait0();
        __syncthreads();
        if (it + 1 < NC/BK) issue((it + 1) & 1, (it + 1)*BK);
        const uint32_t aBase = sb + (uint32_t)((it & 1)*BM*BK)*4u;
        const uint32_t bBase = sb + (uint32_t)(2*BM*BK + (it & 1)*BN*BK)*4u;
        #pragma unroll
        for (int kk = 0; kk < BK; kk += 8) {
            const int c0 = kk >> 2;
            uint32_t a[2][4], b[4][2];
            #pragma unroll
            for (int mt = 0; mt < 2; mt++) {
                int row = wm*32 + mt*16 + (lane & 15);
                int c4  = c0 + (lane >> 4);
                ldsm4(a[mt][0], a[mt][1], a[mt][2], a[mt][3],
                      aBase + 4u*(row*32 + ((c4 ^ (row & 7)) << 2)));
            }
            #pragma unroll
            for (int pq = 0; pq < 2; pq++) {
                int row = wn*32 + ((pq*2 + ((lane >> 4) & 1)) << 3) + (lane & 7);
                int c4  = c0 + ((lane >> 3) & 1);
                ldsm4(b[pq*2][0], b[pq*2][1], b[pq*2+1][0], b[pq*2+1][1],
                      bBase + 4u*(row*32 + ((c4 ^ (row & 7)) << 2)));
            }
            #pragma unroll
            for (int mt = 0; mt < 2; mt++)
                #pragma unroll
                for (int nt = 0; nt < 4; nt++)
                    mma_tf32(acc[mt][nt], a[mt], b[nt]);
        }
    }

    const float bns = rsqrtf(1.0f + 1e-5f);
    __syncthreads();
    float* S = smem;                             // 64*132*4 = 33792 B
    #pragma unroll
    for (int mt = 0; mt < 2; mt++) {
        #pragma unroll
        for (int nt = 0; nt < 4; nt++) {
            int oL = wn*32 + nt*8 + 2*tg;
            int mL = wm*32 + mt*16 + g;
            #pragma unroll
            for (int e = 0; e < 4; e++) {
                int oc = n0 + oL + (e & 1);
                float z = acc[mt][nt][e] + p.bias[oc];
                z = fmaxf(z, 0.0f) * bns;
                S[(oL + (e & 1))*132 + mL + (e >> 1)*8] = z * p.bng[oc] + p.bnb[oc];
            }
        }
    }
    __syncthreads();
    #pragma unroll
    for (int i = 0; i < 8; i++) {
        int idx = tid + i*256;                   // 0..2047
        int oc = idx >> 5;
        int t4 = (idx & 31) * 4;                 // 4-token chunk (NT%4==0)
        int gm = m0 + t4;
        int b = gm / NT, n = gm % NT;
        float4 v = *(float4*)&S[oc*132 + t4];
        *(float4*)(p.Y + ((size_t)b*NC + n0 + oc)*NT + n) = v;
    }
}

// ---------------------------------------------------------------------------
extern "C" void kernel_launch(void* const* d_in, const int* in_sizes, int n_in,
                              void* d_out, int out_size) {
    const float* x1   = (const float*)d_in[0];
    const float* x2   = (const float*)d_in[1];
    const float* Wq1  = (const float*)d_in[2];
    const float* bq1  = (const float*)d_in[3];
    const float* Wk1  = (const float*)d_in[4];
    const float* bk1  = (const float*)d_in[5];
    const float* Wv1  = (const float*)d_in[6];
    const float* bv1  = (const float*)d_in[7];
    const float* ln1g = (const float*)d_in[8];
    const float* ln1b = (const float*)d_in[9];
    const float* Wq2  = (const float*)d_in[10];
    const float* bq2  = (const float*)d_in[11];
    const float* Wk2  = (const float*)d_in[12];
    const float* bk2  = (const float*)d_in[13];
    const float* Wv2  = (const float*)d_in[14];
    const float* bv2  = (const float*)d_in[15];
    const float* ln2g = (const float*)d_in[16];
    const float* ln2b = (const float*)d_in[17];
    const float* o1w  = (const float*)d_in[18];
    const float* o1b  = (const float*)d_in[19];
    const float* bn1g = (const float*)d_in[20];
    const float* bn1b = (const float*)d_in[21];
    const float* o2w  = (const float*)d_in[22];
    const float* o2b  = (const float*)d_in[23];
    const float* bn2g = (const float*)d_in[24];
    const float* bn2b = (const float*)d_in[25];
    float* out = (float*)d_out;

    float *t1, *t2, *t1f, *t2f, *wf;
    void *th1, *th2, *ln1h, *ln2h, *q1h, *k1h, *v1h, *q2h, *k2h, *v2h, *wh;
    cudaGetSymbolAddress((void**)&t1,  g_t1);
    cudaGetSymbolAddress((void**)&t2,  g_t2);
    cudaGetSymbolAddress((void**)&t1f, g_t1f);
    cudaGetSymbolAddress((void**)&t2f, g_t2f);
    cudaGetSymbolAddress(&th1,  g_th1);
    cudaGetSymbolAddress(&th2,  g_th2);
    cudaGetSymbolAddress(&ln1h, g_ln1h);
    cudaGetSymbolAddress(&ln2h, g_ln2h);
    cudaGetSymbolAddress(&q1h, g_q1h);
    cudaGetSymbolAddress(&k1h, g_k1h);
    cudaGetSymbolAddress(&v1h, g_v1h);
    cudaGetSymbolAddress(&q2h, g_q2h);
    cudaGetSymbolAddress(&k2h, g_k2h);
    cudaGetSymbolAddress(&v2h, g_v2h);
    cudaGetSymbolAddress(&wh,  g_wh);
    cudaGetSymbolAddress((void**)&wf, g_wf);
    __nv_bfloat16 *TH1 = (__nv_bfloat16*)th1, *TH2 = (__nv_bfloat16*)th2;
    __nv_bfloat16 *LN1 = (__nv_bfloat16*)ln1h, *LN2 = (__nv_bfloat16*)ln2h;
    __nv_bfloat16 *WH = (__nv_bfloat16*)wh;
    __nv_bfloat16 *Q1 = (__nv_bfloat16*)q1h, *K1 = (__nv_bfloat16*)k1h;
    __nv_bfloat16 *Q2 = (__nv_bfloat16*)q2h, *K2 = (__nv_bfloat16*)k2h;
    __half *V1 = (__half*)v1h, *V2 = (__half*)v2h;

    const int OUT_SMEM = 49152;
    cudaFuncSetAttribute(gemm_proj, cudaFuncAttributeMaxDynamicSharedMemorySize, PROJ_SMEM_BYTES);
    cudaFuncSetAttribute(gemm_out,  cudaFuncAttributeMaxDynamicSharedMemorySize, OUT_SMEM);
    cudaFuncSetAttribute(attn_bf,   cudaFuncAttributeMaxDynamicSharedMemorySize, ATTN_SMEM_BYTES);

    WPtrs wp;
    wp.p[0] = Wq1; wp.p[1] = Wk1; wp.p[2] = Wv1;
    wp.p[3] = Wq2; wp.p[4] = Wk2; wp.p[5] = Wv2;
    wp.p[6] = o1w; wp.p[7] = o2w;
    wcvt_kernel<<<dim3(N2/1024, 20), 256>>>(wp, WH, wf);

    dim3 tokGrid(NT/32, NC/32, 2*NB), tokBlk(32, 8);
    tok_kernel<<<tokGrid, tokBlk>>>(x1, t1, TH1, x2, t2, TH2);

    dim3 pGrid(NC/128, NM/128, 6);          // (4, 49, 6)
    dim3 aGrid((NT + 127)/128, NH, 2*NB);   // (13, 8, 8)
    dim3 oGrid(NC/64, NM/128, 2);           // (8, 49, 2)
    const float qs = 0.125f * LOG2E, one = 1.0f;

    for (int i = 0; i < 3; i++) {
        ln_kernel<<<dim3(NM/8, 2), 256>>>(t1, ln1g + i*NC, ln1b + i*NC, LN1,
                                          t2, ln2g + i*NC, ln2b + i*NC, LN2);
        PArgs pa;
        pa.op[0] = { LN1, WH + (size_t)(0*3 + i)*N2, bq1 + i*NC, Q1, qs,  0 };
        pa.op[1] = { TH2, WH + (size_t)(1*3 + i)*N2, bk1 + i*NC, K1, one, 0 };
        pa.op[2] = { TH2, WH + (size_t)(2*3 + i)*N2, bv1 + i*NC, V1, one, 1 };
        pa.op[3] = { LN2, WH + (size_t)(3*3 + i)*N2, bq2 + i*NC, Q2, qs,  0 };
        pa.op[4] = { TH1, WH + (size_t)(4*3 + i)*N2, bk2 + i*NC, K2, one, 0 };
        pa.op[5] = { TH1, WH + (size_t)(5*3 + i)*N2, bv2 + i*NC, V2, one, 1 };
        gemm_proj<<<pGrid, 256, PROJ_SMEM_BYTES>>>(pa);

        bool last = (i == 2);
        AArgs aa;
        aa.Q[0] = Q1;  aa.Q[1] = Q2;
        aa.K[0] = K1;  aa.K[1] = K2;
        aa.Vt[0] = V1; aa.Vt[1] = V2;
        aa.T[0] = t1;  aa.T[1] = t2;
        aa.Th[0] = last ? nullptr : TH1;  aa.Th[1] = last ? nullptr : TH2;
        aa.Tf[0] = last ? t1f : nullptr;  aa.Tf[1] = last ? t2f : nullptr;
        attn_bf<<<aGrid, 256, ATTN_SMEM_BYTES>>>(aa);
    }

    OArgs oa;
    oa.op[0] = { t1f, wf,      o1b, bn1g, bn1b, out };
    oa.op[1] = { t2f, wf + N2, o2b, bn2g, bn2b, out + (size_t)NB*NC*NT };
    gemm_out<<<oGrid, 256, OUT_SMEM>>>(oa);
}